// round 4
// baseline (speedup 1.0000x reference)
#include <cuda_runtime.h>
#include <cuda_bf16.h>
#include <cstdint>
#include <cstddef>

#define NMAX   100000
#define EMAX   300000
#define VMAX   50000
#define HMAX   1152
#define OUTMAX 576
#define EPS    1e-5f

// ---------------- static scratch ----------------
// g_H holds: 196-dim embedding, BN outputs (up to 384), dist outputs (up to 384).
// Sized for 576 to cover every intermediate width with headroom.
__device__ float g_H [(size_t)NMAX * OUTMAX];
__device__ float g_PQ[(size_t)NMAX * 2 * HMAX];
__device__ float g_T [(size_t)NMAX * HMAX];
__device__ float g_U [(size_t)NMAX * OUTMAX];
__device__ float g_W [384 * 2 * HMAX];
__device__ float g_bc[2 * HMAX];
__device__ float g_vsum[(size_t)VMAX * (OUTMAX / 3)];
__device__ float g_stat[2 * OUTMAX];
__device__ float g_rscale[NMAX];
__device__ int   g_deg[NMAX];
__device__ int   g_offs[NMAX + 1];
__device__ int   g_cur[NMAX];
__device__ int   g_csr[EMAX];
__device__ int   g_vcnt[VMAX];

// ---------------- f32x2 helpers ----------------
__device__ __forceinline__ unsigned long long f2_dup(float x) {
    unsigned long long r;
    asm("mov.b64 %0, {%1, %1};" : "=l"(r) : "f"(x));
    return r;
}
__device__ __forceinline__ unsigned long long f2_fma(unsigned long long a,
                                                     unsigned long long b,
                                                     unsigned long long c) {
    unsigned long long d;
    asm("fma.rn.f32x2 %0, %1, %2, %3;" : "=l"(d) : "l"(a), "l"(b), "l"(c));
    return d;
}
__device__ __forceinline__ void f2_unpack(unsigned long long p, float& lo, float& hi) {
    asm("mov.b64 {%0, %1}, %2;" : "=f"(lo), "=f"(hi) : "l"(p));
}

// ---------------- utility kernels ----------------
__global__ void zero_f_kernel(float* p, size_t n) {
    size_t i = (size_t)blockIdx.x * blockDim.x + threadIdx.x;
    if (i < n) p[i] = 0.f;
}
__global__ void zero_i_kernel(int* p, int n) {
    int i = blockIdx.x * blockDim.x + threadIdx.x;
    if (i < n) p[i] = 0;
}

// ---------------- embed ----------------
__global__ void embed_kernel(const float* __restrict__ x, float* __restrict__ H, int N) {
    int n = blockIdx.x * blockDim.x + threadIdx.x;
    if (n >= N) return;
    const float* xr = x + (size_t)n * 16;
    float* h = H + (size_t)n * 196;
#pragma unroll
    for (int g = 0; g < 3; g++) {
        const float* p = xr + g * 3;
        float* o = h + g * 63;
        o[0] = p[0]; o[1] = p[1]; o[2] = p[2];
#pragma unroll
        for (int c = 0; c < 3; c++) {
            float f = 1.f;
#pragma unroll
            for (int q = 0; q < 10; q++) {
                float ang = p[c] * f;
                o[3 + c * 20 + q * 2]     = sinf(ang);
                o[3 + c * 20 + q * 2 + 1] = cosf(ang);
                f *= 2.f;
            }
        }
    }
#pragma unroll
    for (int k = 0; k < 7; k++) h[189 + k] = xr[9 + k];
}

// ---------------- CSR build ----------------
__global__ void count_deg_kernel(const int* __restrict__ ei, int* __restrict__ deg, int E) {
    int e = blockIdx.x * blockDim.x + threadIdx.x;
    if (e < E) atomicAdd(&deg[ei[E + e]], 1);
}

__global__ void scan_kernel(const int* __restrict__ deg, int* __restrict__ offs,
                            int* __restrict__ cur, float* __restrict__ rscale, int N) {
    __shared__ int part[1024];
    int t = threadIdx.x;
    int chunk = (N + 1023) >> 10;
    int lo = t * chunk;
    int hi = lo + chunk; if (hi > N) hi = N;
    if (lo > N) lo = N;
    int s = 0;
    for (int i = lo; i < hi; i++) s += deg[i];
    part[t] = s;
    __syncthreads();
    for (int off = 1; off < 1024; off <<= 1) {
        int v = (t >= off) ? part[t - off] : 0;
        __syncthreads();
        part[t] += v;
        __syncthreads();
    }
    int base = (t == 0) ? 0 : part[t - 1];
    for (int i = lo; i < hi; i++) {
        offs[i] = base;
        cur[i] = base;
        int d = deg[i];
        rscale[i] = d > 0 ? 1.f / (float)d : 0.f;
        base += d;
    }
    if (t == 1023) offs[N] = part[1023];
}

__global__ void fill_csr_kernel(const int* __restrict__ ei, int* __restrict__ cur,
                                int* __restrict__ csr, int E) {
    int e = blockIdx.x * blockDim.x + threadIdx.x;
    if (e < E) {
        int d = ei[E + e];
        int pos = atomicAdd(&cur[d], 1);
        csr[pos] = ei[e];
    }
}

__global__ void vcnt_kernel(const int* __restrict__ faces, int* __restrict__ vcnt, int n3) {
    int t = blockIdx.x * blockDim.x + threadIdx.x;
    if (t < n3) atomicAdd(&vcnt[faces[t]], 1);
}

// ---------------- weight prep ----------------
__global__ void prep_w_kernel(const float* __restrict__ w1, float* __restrict__ W,
                              int F, int hid) {
    int t = blockIdx.x * blockDim.x + threadIdx.x;
    int n = F * 2 * hid;
    if (t >= n) return;
    int k = t / (2 * hid);
    int j = t % (2 * hid);
    float bot = w1[(size_t)(F + k) * hid + (j < hid ? j : j - hid)];
    if (j < hid) {
        W[t] = w1[(size_t)k * hid + j] - bot;
    } else {
        W[t] = bot;
    }
}
__global__ void prep_b_kernel(const float* __restrict__ b1, float* __restrict__ bc, int hid) {
    int j = blockIdx.x * blockDim.x + threadIdx.x;
    if (j < 2 * hid) bc[j] = (j < hid) ? b1[j] : 0.f;
}

// ---------------- GEMM: C[M,Nc] = A[M,K] @ B[K,Nc] (+epilogue) ----------------
template <bool SCALED>
__global__ __launch_bounds__(256, 2)
void gemm_kernel(const float* __restrict__ A, const float* __restrict__ B,
                 float* __restrict__ C, int M, int K, int Nc,
                 const float* __restrict__ bias, const float* __restrict__ rowscale) {
    __shared__ __align__(16) float As[16][130];
    __shared__ __align__(16) float Bs[16][128];

    const int tid = threadIdx.x;
    const int tx = tid & 15;
    const int ty = tid >> 4;
    const int rowBase = blockIdx.y << 7;
    const int colBase = blockIdx.x << 7;

    unsigned long long acc[4][8];
#pragma unroll
    for (int p = 0; p < 4; p++)
#pragma unroll
        for (int j = 0; j < 8; j++) acc[p][j] = 0ull;

    for (int k0 = 0; k0 < K; k0 += 16) {
        // A tile: 128 rows x 16 k, stored transposed
#pragma unroll
        for (int i = 0; i < 2; i++) {
            int q = tid + (i << 8);
            int ar = q >> 2;
            int ak = (q & 3) << 2;
            float4 av = make_float4(0.f, 0.f, 0.f, 0.f);
            int gr = rowBase + ar;
            int gk = k0 + ak;
            if (gr < M && gk < K) av = *(const float4*)(A + (size_t)gr * K + gk);
            As[ak + 0][ar] = av.x;
            As[ak + 1][ar] = av.y;
            As[ak + 2][ar] = av.z;
            As[ak + 3][ar] = av.w;
        }
        // B tile: 16 k x 128 cols
#pragma unroll
        for (int i = 0; i < 2; i++) {
            int q = tid + (i << 8);
            int br = q >> 5;
            int bcc = (q & 31) << 2;
            float4 bv = make_float4(0.f, 0.f, 0.f, 0.f);
            int gk = k0 + br;
            int gc = colBase + bcc;
            if (gk < K && gc < Nc) bv = *(const float4*)(B + (size_t)gk * Nc + gc);
            *(float4*)&Bs[br][bcc] = bv;
        }
        __syncthreads();

#pragma unroll
        for (int kk = 0; kk < 16; kk++) {
            float4 b4a = *(const float4*)&Bs[kk][tx * 4];
            float4 b4b = *(const float4*)&Bs[kk][64 + tx * 4];
            unsigned long long bb[8];
            bb[0] = f2_dup(b4a.x); bb[1] = f2_dup(b4a.y);
            bb[2] = f2_dup(b4a.z); bb[3] = f2_dup(b4a.w);
            bb[4] = f2_dup(b4b.x); bb[5] = f2_dup(b4b.y);
            bb[6] = f2_dup(b4b.z); bb[7] = f2_dup(b4b.w);
            unsigned long long av[4];
#pragma unroll
            for (int p = 0; p < 4; p++)
                av[p] = *(const unsigned long long*)&As[kk][ty * 8 + 2 * p];
#pragma unroll
            for (int p = 0; p < 4; p++)
#pragma unroll
                for (int j = 0; j < 8; j++)
                    acc[p][j] = f2_fma(av[p], bb[j], acc[p][j]);
        }
        __syncthreads();
    }

    // epilogue
#pragma unroll
    for (int p = 0; p < 4; p++) {
        int r0 = rowBase + ty * 8 + 2 * p;
        int r1 = r0 + 1;
        float rs0 = 1.f, rs1 = 1.f, bf0 = 1.f, bf1 = 1.f;
        if (SCALED) {
            if (r0 < M) { rs0 = rowscale[r0]; bf0 = rs0 > 0.f ? 1.f : 0.f; }
            if (r1 < M) { rs1 = rowscale[r1]; bf1 = rs1 > 0.f ? 1.f : 0.f; }
        }
#pragma unroll
        for (int j = 0; j < 8; j++) {
            int col = colBase + ((j < 4) ? (tx * 4 + j) : (64 + tx * 4 + (j - 4)));
            if (col >= Nc) continue;
            float lo, hi;
            f2_unpack(acc[p][j], lo, hi);
            float bv = bias[col];
            if (r0 < M) C[(size_t)r0 * Nc + col] = SCALED ? (rs0 * lo + bf0 * bv) : (lo + bv);
            if (r1 < M) C[(size_t)r1 * Nc + col] = SCALED ? (rs1 * hi + bf1 * bv) : (hi + bv);
        }
    }
}

// ---------------- edge aggregation: T[v] = sum_e relu(P[v] + Q[src_e]) ----------------
__global__ void edge_agg_kernel(const float* __restrict__ PQ, const int* __restrict__ offs,
                                const int* __restrict__ csr, float* __restrict__ T, int hid) {
    __shared__ int ssrc[1024];
    int v = blockIdx.x;
    int beg = offs[v];
    int end = offs[v + 1];
    int deg = end - beg;
    int tid = threadIdx.x;
    int cached = deg < 1024 ? deg : 1024;
    for (int e = tid; e < cached; e += blockDim.x) ssrc[e] = csr[beg + e];
    __syncthreads();
    const float* Prow = PQ + (size_t)v * (2 * hid);
    float* Trow = T + (size_t)v * hid;
    for (int c = tid; c < hid; c += blockDim.x) {
        float p = Prow[c];
        float a = 0.f;
        for (int e = 0; e < deg; e++) {
            int s = (e < 1024) ? ssrc[e] : csr[beg + e];
            float t2 = p + PQ[(size_t)s * (2 * hid) + hid + c];
            a += t2 > 0.f ? t2 : 0.f;
        }
        Trow[c] = a;
    }
}

// ---------------- BatchNorm ----------------
__global__ void bn_stats_kernel(const float* __restrict__ X, float* __restrict__ stat,
                                int N, int F) {
    int tid = threadIdx.x;
    int c0 = tid, c1 = tid + 256;
    float s0 = 0.f, s1 = 0.f, q0 = 0.f, q1 = 0.f;
    for (int row = blockIdx.x; row < N; row += gridDim.x) {
        const float* r = X + (size_t)row * F;
        if (c0 < F) { float v = r[c0]; s0 += v; q0 += v * v; }
        if (c1 < F) { float v = r[c1]; s1 += v; q1 += v * v; }
    }
    if (c0 < F) { atomicAdd(&stat[c0], s0); atomicAdd(&stat[F + c0], q0); }
    if (c1 < F) { atomicAdd(&stat[c1], s1); atomicAdd(&stat[F + c1], q1); }
}

__global__ void bn_apply_kernel(const float* __restrict__ X, const float* __restrict__ stat,
                                const float* __restrict__ gamma, const float* __restrict__ beta,
                                float* __restrict__ Y, int N, int F) {
    size_t t = (size_t)blockIdx.x * blockDim.x + threadIdx.x;
    size_t n = (size_t)N * F;
    if (t >= n) return;
    int c = (int)(t % F);
    float invN = 1.f / (float)N;
    float mu = stat[c] * invN;
    float var = stat[F + c] * invN - mu * mu;
    float sc = rsqrtf(var + EPS) * gamma[c];
    float y = (X[t] - mu) * sc + beta[c];
    Y[t] = y > 0.f ? y : 0.f;
}

// ---------------- distribute_features ----------------
__global__ void dist_scatter_kernel(const float* __restrict__ feat, const int* __restrict__ idx,
                                    float* __restrict__ vsum, int n3, int F3) {
    size_t t = (size_t)blockIdx.x * blockDim.x + threadIdx.x;
    size_t n = (size_t)n3 * F3;
    if (t >= n) return;
    int r = (int)(t / F3);
    int c = (int)(t % F3);
    atomicAdd(&vsum[(size_t)idx[r] * F3 + c], feat[t]);
}

__global__ void dist_gather_kernel(const float* __restrict__ vsum, const int* __restrict__ vcnt,
                                   const int* __restrict__ idx, float* __restrict__ out,
                                   int n3, int F3) {
    size_t t = (size_t)blockIdx.x * blockDim.x + threadIdx.x;
    size_t n = (size_t)n3 * F3;
    if (t >= n) return;
    int r = (int)(t / F3);
    int c = (int)(t % F3);
    int v = idx[r];
    float cn = (float)vcnt[v];
    out[t] = vsum[(size_t)v * F3 + c] / (cn > 0.f ? cn : 1.f);
}

// ---------------- host ----------------
static inline int ceil_div(long long a, int b) { return (int)((a + b - 1) / b); }

extern "C" void kernel_launch(void* const* d_in, const int* in_sizes, int n_in,
                              void* d_out, int out_size) {
    const float* x     = (const float*)d_in[0];
    const int*   ei    = (const int*)d_in[1];
    const int*   faces = (const int*)d_in[2];
    int argbase = (n_in >= 32) ? 4 : 3;

    int N = in_sizes[0] / 16;
    int E = in_sizes[1] / 2;
    int n3 = N * 3;

    float *H, *PQ, *T, *U, *W, *bc, *vsum, *stat, *rscale;
    int *deg, *offs, *cur, *csr, *vcnt;
    cudaGetSymbolAddress((void**)&H, g_H);
    cudaGetSymbolAddress((void**)&PQ, g_PQ);
    cudaGetSymbolAddress((void**)&T, g_T);
    cudaGetSymbolAddress((void**)&U, g_U);
    cudaGetSymbolAddress((void**)&W, g_W);
    cudaGetSymbolAddress((void**)&bc, g_bc);
    cudaGetSymbolAddress((void**)&vsum, g_vsum);
    cudaGetSymbolAddress((void**)&stat, g_stat);
    cudaGetSymbolAddress((void**)&rscale, g_rscale);
    cudaGetSymbolAddress((void**)&deg, g_deg);
    cudaGetSymbolAddress((void**)&offs, g_offs);
    cudaGetSymbolAddress((void**)&cur, g_cur);
    cudaGetSymbolAddress((void**)&csr, g_csr);
    cudaGetSymbolAddress((void**)&vcnt, g_vcnt);

    // CSR (by dst) + vertex counts
    zero_i_kernel<<<ceil_div(N, 256), 256>>>(deg, N);
    count_deg_kernel<<<ceil_div(E, 256), 256>>>(ei, deg, E);
    scan_kernel<<<1, 1024>>>(deg, offs, cur, rscale, N);
    fill_csr_kernel<<<ceil_div(E, 256), 256>>>(ei, cur, csr, E);
    zero_i_kernel<<<ceil_div(VMAX, 256), 256>>>(vcnt, VMAX);
    vcnt_kernel<<<ceil_div(n3, 256), 256>>>(faces, vcnt, n3);

    // embedding -> H [N,196]
    embed_kernel<<<ceil_div(N, 128), 128>>>(x, H, N);

    struct LCfg { int F, hid, out; };
    const LCfg ls[5] = {
        {196, 192, 96}, {96, 384, 192}, {192, 768, 384}, {384, 768, 384}, {384, 1152, 576}
    };

    const float* cur_in = H;
    for (int L = 0; L < 5; L++) {
        const LCfg& cf = ls[L];
        const float* w1 = (const float*)d_in[argbase + 4 * L + 0];
        const float* b1 = (const float*)d_in[argbase + 4 * L + 1];
        const float* w2 = (const float*)d_in[argbase + 4 * L + 2];
        const float* b2 = (const float*)d_in[argbase + 4 * L + 3];

        // fused weight [F, 2*hid] and bias [2*hid]
        prep_w_kernel<<<ceil_div((long long)cf.F * 2 * cf.hid, 256), 256>>>(w1, W, cf.F, cf.hid);
        prep_b_kernel<<<ceil_div(2 * cf.hid, 256), 256>>>(b1, bc, cf.hid);

        // PQ = cur_in @ W + bc   [N, 2*hid]
        {
            dim3 grid(ceil_div(2 * cf.hid, 128), ceil_div(N, 128));
            gemm_kernel<false><<<grid, 256>>>(cur_in, W, PQ, N, cf.F, 2 * cf.hid, bc, nullptr);
        }

        // T[v] = sum_e relu(P[v] + Q[src])   [N, hid]
        edge_agg_kernel<<<N, 128>>>(PQ, offs, csr, T, cf.hid);

        // U = rowscale * (T @ w2) + (deg>0)*b2   [N, out]
        {
            dim3 grid(ceil_div(cf.out, 128), ceil_div(N, 128));
            gemm_kernel<true><<<grid, 256>>>(T, w2, U, N, cf.hid, cf.out, b2, rscale);
        }

        const float* dist_in;
        if (L < 4) {
            const float* gamma = (const float*)d_in[argbase + 20 + 2 * L];
            const float* beta  = (const float*)d_in[argbase + 20 + 2 * L + 1];
            zero_f_kernel<<<ceil_div(2 * cf.out, 256), 256>>>(stat, 2 * cf.out);
            bn_stats_kernel<<<512, 256>>>(U, stat, N, cf.out);
            bn_apply_kernel<<<ceil_div((long long)N * cf.out, 256), 256>>>(
                U, stat, gamma, beta, H, N, cf.out);
            dist_in = H;
        } else {
            dist_in = U;
        }

        // distribute_features
        int F3 = cf.out / 3;
        float* dist_out = (L == 4) ? (float*)d_out : H;
        zero_f_kernel<<<ceil_div((long long)VMAX * F3, 256), 256>>>(vsum, (size_t)VMAX * F3);
        dist_scatter_kernel<<<ceil_div((long long)n3 * F3, 256), 256>>>(dist_in, faces, vsum, n3, F3);
        dist_gather_kernel<<<ceil_div((long long)n3 * F3, 256), 256>>>(vsum, vcnt, faces, dist_out, n3, F3);

        cur_in = H;
    }
}

// round 7
// speedup vs baseline: 1.1410x; 1.1410x over previous
#include <cuda_runtime.h>
#include <cuda_bf16.h>
#include <cstdint>
#include <cstddef>

#define NMAX   100000
#define EMAX   300000
#define VMAX   50000
#define HMAX   1152
#define OUTMAX 576
#define EPS    1e-5f

// ---------------- static scratch ----------------
__device__ float g_H [(size_t)NMAX * OUTMAX];             // BN outputs (f32) for dist_scatter
__device__ float g_PQ[(size_t)NMAX * 2 * HMAX];           // [P | Q] per node (f32)
__device__ float g_U [(size_t)NMAX * OUTMAX];             // edge_conv output (f32)
__device__ __nv_bfloat16 g_Ahi[(size_t)NMAX * HMAX];      // activation hi (bf16, padded K)
__device__ __nv_bfloat16 g_Alo[(size_t)NMAX * HMAX];      // activation lo
__device__ __nv_bfloat16 g_Bhi[1048576];                  // weight hi [Nc][Kp]
__device__ __nv_bfloat16 g_Blo[1048576];                  // weight lo
__device__ float g_bc[2 * HMAX];
__device__ float g_vsum[(size_t)VMAX * (OUTMAX / 3)];
__device__ float g_stat[2 * OUTMAX];
__device__ float g_rscale[NMAX];
__device__ int   g_deg[NMAX];
__device__ int   g_offs[NMAX + 1];
__device__ int   g_cur[NMAX];
__device__ int   g_csr[EMAX];
__device__ int   g_vcnt[VMAX];

// ---------------- helpers ----------------
__device__ __forceinline__ uint32_t smem_u32(const void* p) {
    uint32_t a;
    asm("{ .reg .u64 t; cvta.to.shared.u64 t, %1; cvt.u32.u64 %0, t; }" : "=r"(a) : "l"(p));
    return a;
}

__device__ __forceinline__ void mma_bf16(float* c, const uint32_t* a, uint32_t b0, uint32_t b1) {
    asm volatile(
        "mma.sync.aligned.m16n8k16.row.col.f32.bf16.bf16.f32 "
        "{%0,%1,%2,%3}, {%4,%5,%6,%7}, {%8,%9}, {%0,%1,%2,%3};"
        : "+f"(c[0]), "+f"(c[1]), "+f"(c[2]), "+f"(c[3])
        : "r"(a[0]), "r"(a[1]), "r"(a[2]), "r"(a[3]), "r"(b0), "r"(b1));
}

__device__ __forceinline__ void split_write(float v, __nv_bfloat16* hi, __nv_bfloat16* lo, size_t i) {
    __nv_bfloat16 h = __float2bfloat16(v);
    hi[i] = h;
    lo[i] = __float2bfloat16(v - __bfloat162float(h));
}

// ---------------- utility kernels ----------------
__global__ void zero_f_kernel(float* p, size_t n) {
    size_t i = (size_t)blockIdx.x * blockDim.x + threadIdx.x;
    if (i < n) p[i] = 0.f;
}
__global__ void zero_i_kernel(int* p, int n) {
    int i = blockIdx.x * blockDim.x + threadIdx.x;
    if (i < n) p[i] = 0;
}
__global__ void pad_split_kernel(__nv_bfloat16* hi, __nv_bfloat16* lo, int N, int F, int stride) {
    int padw = stride - F;
    int t = blockIdx.x * blockDim.x + threadIdx.x;
    int n = N * padw;
    if (t >= n) return;
    int node = t / padw;
    int c = F + (t % padw);
    size_t i = (size_t)node * stride + c;
    hi[i] = __float2bfloat16(0.f);
    lo[i] = __float2bfloat16(0.f);
}

// ---------------- embed -> split bf16 [N x 256] (196 valid, padded) ----------------
__global__ void embed_split_kernel(const float* __restrict__ x,
                                   __nv_bfloat16* __restrict__ hi,
                                   __nv_bfloat16* __restrict__ lo, int N) {
    int n = blockIdx.x * blockDim.x + threadIdx.x;
    if (n >= N) return;
    const float* xr = x + (size_t)n * 16;
    size_t base = (size_t)n * 256;
#pragma unroll
    for (int g = 0; g < 3; g++) {
        const float* p = xr + g * 3;
        size_t o = base + g * 63;
        split_write(p[0], hi, lo, o + 0);
        split_write(p[1], hi, lo, o + 1);
        split_write(p[2], hi, lo, o + 2);
#pragma unroll
        for (int c = 0; c < 3; c++) {
            float f = 1.f;
#pragma unroll
            for (int q = 0; q < 10; q++) {
                float ang = p[c] * f;
                split_write(sinf(ang), hi, lo, o + 3 + c * 20 + q * 2);
                split_write(cosf(ang), hi, lo, o + 3 + c * 20 + q * 2 + 1);
                f *= 2.f;
            }
        }
    }
#pragma unroll
    for (int k = 0; k < 7; k++) split_write(xr[9 + k], hi, lo, base + 189 + k);
#pragma unroll
    for (int k = 196; k < 256; k++) { hi[base + k] = __float2bfloat16(0.f); lo[base + k] = __float2bfloat16(0.f); }
}

// ---------------- CSR build ----------------
__global__ void count_deg_kernel(const int* __restrict__ ei, int* __restrict__ deg, int E) {
    int e = blockIdx.x * blockDim.x + threadIdx.x;
    if (e < E) atomicAdd(&deg[ei[E + e]], 1);
}

__global__ void scan_kernel(const int* __restrict__ deg, int* __restrict__ offs,
                            int* __restrict__ cur, float* __restrict__ rscale, int N) {
    __shared__ int part[1024];
    int t = threadIdx.x;
    int chunk = (N + 1023) >> 10;
    int lo = t * chunk;
    int hi = lo + chunk; if (hi > N) hi = N;
    if (lo > N) lo = N;
    int s = 0;
    for (int i = lo; i < hi; i++) s += deg[i];
    part[t] = s;
    __syncthreads();
    for (int off = 1; off < 1024; off <<= 1) {
        int v = (t >= off) ? part[t - off] : 0;
        __syncthreads();
        part[t] += v;
        __syncthreads();
    }
    int base = (t == 0) ? 0 : part[t - 1];
    for (int i = lo; i < hi; i++) {
        offs[i] = base;
        cur[i] = base;
        int d = deg[i];
        rscale[i] = d > 0 ? 1.f / (float)d : 0.f;
        base += d;
    }
    if (t == 1023) offs[N] = part[1023];
}

__global__ void fill_csr_kernel(const int* __restrict__ ei, int* __restrict__ cur,
                                int* __restrict__ csr, int E) {
    int e = blockIdx.x * blockDim.x + threadIdx.x;
    if (e < E) {
        int d = ei[E + e];
        int pos = atomicAdd(&cur[d], 1);
        csr[pos] = ei[e];
    }
}

__global__ void vcnt_kernel(const int* __restrict__ faces, int* __restrict__ vcnt, int n3) {
    int t = blockIdx.x * blockDim.x + threadIdx.x;
    if (t < n3) atomicAdd(&vcnt[faces[t]], 1);
}

// ---------------- weight prep (fused + transposed + split) ----------------
__global__ void prep_w_split_kernel(const float* __restrict__ w1,
                                    __nv_bfloat16* __restrict__ hi,
                                    __nv_bfloat16* __restrict__ lo,
                                    int F, int hid, int Kp) {
    int t = blockIdx.x * blockDim.x + threadIdx.x;
    int n = 2 * hid * Kp;
    if (t >= n) return;
    int j = t / Kp;
    int k = t % Kp;
    float v = 0.f;
    if (k < F) {
        if (j < hid) v = w1[(size_t)k * hid + j] - w1[(size_t)(F + k) * hid + j];
        else         v = w1[(size_t)(F + k) * hid + (j - hid)];
    }
    split_write(v, hi, lo, t);
}
__global__ void prep_w2t_split_kernel(const float* __restrict__ w2,
                                      __nv_bfloat16* __restrict__ hi,
                                      __nv_bfloat16* __restrict__ lo,
                                      int hid, int out, int Kp) {
    int t = blockIdx.x * blockDim.x + threadIdx.x;
    int n = out * Kp;
    if (t >= n) return;
    int j = t / Kp;
    int k = t % Kp;
    float v = (k < hid) ? w2[(size_t)k * out + j] : 0.f;
    split_write(v, hi, lo, t);
}
__global__ void prep_b_kernel(const float* __restrict__ b1, float* __restrict__ bc, int hid) {
    int j = blockIdx.x * blockDim.x + threadIdx.x;
    if (j < 2 * hid) bc[j] = (j < hid) ? b1[j] : 0.f;
}

// ---------------- mma.sync split-bf16 GEMM ----------------
// C[M,Nc] = (Ahi+Alo)[M,Kp] @ (Bhi+Blo)^T[Kp,Nc]   (B stored [Nc][Kp], K-major)
// CTA tile 128x128, BK=32, 8 warps (2x4), warp tile 64x32.
// smem pitch 40 bf16 (80 B): 16B-aligned rows, ldmatrix bank-conflict-free.
#define SPITCH 40

__device__ __forceinline__ void load_tile32(__nv_bfloat16* S, const __nv_bfloat16* __restrict__ G,
                                            int rowBase, int rowMax, int Kp, int k0, int tid) {
#pragma unroll
    for (int i = 0; i < 2; i++) {
        int idx = tid + (i << 8);          // 0..511
        int r = idx >> 2;
        int c8 = (idx & 3) << 3;
        uint4 v = make_uint4(0u, 0u, 0u, 0u);
        int gr = rowBase + r;
        if (gr < rowMax) v = *(const uint4*)(G + (size_t)gr * Kp + k0 + c8);
        *(uint4*)(S + r * SPITCH + c8) = v;
    }
}

__device__ __forceinline__ void gemm_pass(uint32_t sA, uint32_t sB, float acc[4][4][4],
                                          int mBase, int nBase, int laneRow, int laneK8) {
#pragma unroll
    for (int k16 = 0; k16 < 32; k16 += 16) {
        uint32_t a[4][4];
#pragma unroll
        for (int im = 0; im < 4; im++) {
            uint32_t addr = sA + (uint32_t)(((mBase + im * 16 + laneRow) * SPITCH + k16 + laneK8) * 2);
            asm volatile("ldmatrix.sync.aligned.m8n8.x4.shared.b16 {%0,%1,%2,%3}, [%4];"
                         : "=r"(a[im][0]), "=r"(a[im][1]), "=r"(a[im][2]), "=r"(a[im][3])
                         : "r"(addr));
        }
        uint32_t b[2][4];
#pragma unroll
        for (int in2 = 0; in2 < 2; in2++) {
            uint32_t addr = sB + (uint32_t)(((nBase + in2 * 16 + laneRow) * SPITCH + k16 + laneK8) * 2);
            asm volatile("ldmatrix.sync.aligned.m8n8.x4.shared.b16 {%0,%1,%2,%3}, [%4];"
                         : "=r"(b[in2][0]), "=r"(b[in2][1]), "=r"(b[in2][2]), "=r"(b[in2][3])
                         : "r"(addr));
        }
#pragma unroll
        for (int im = 0; im < 4; im++) {
#pragma unroll
            for (int in2 = 0; in2 < 2; in2++) {
                mma_bf16(acc[im][in2 * 2 + 0], a[im], b[in2][0], b[in2][2]);
                mma_bf16(acc[im][in2 * 2 + 1], a[im], b[in2][1], b[in2][3]);
            }
        }
    }
}

template <bool SCALED>
__global__ void __launch_bounds__(256)
gemm_mma(const __nv_bfloat16* __restrict__ Ahi, const __nv_bfloat16* __restrict__ Alo,
         const __nv_bfloat16* __restrict__ Bhi, const __nv_bfloat16* __restrict__ Blo,
         float* __restrict__ C, int M, int Kp, int Nc,
         const float* __restrict__ bias, const float* __restrict__ rowscale) {
    __shared__ __align__(16) __nv_bfloat16 sAhi[128 * SPITCH];
    __shared__ __align__(16) __nv_bfloat16 sAlo[128 * SPITCH];
    __shared__ __align__(16) __nv_bfloat16 sBhi[128 * SPITCH];
    __shared__ __align__(16) __nv_bfloat16 sBlo[128 * SPITCH];

    const int tid = threadIdx.x;
    const int wid = tid >> 5;
    const int lane = tid & 31;
    const int colBase = blockIdx.x << 7;
    const int rowBase = blockIdx.y << 7;
    const int mBase = (wid >> 2) * 64;
    const int nBase = (wid & 3) * 32;
    const int laneRow = lane & 15;
    const int laneK8 = (lane >> 4) << 3;

    uint32_t uAhi = smem_u32(sAhi), uAlo = smem_u32(sAlo);
    uint32_t uBhi = smem_u32(sBhi), uBlo = smem_u32(sBlo);

    float acc[4][4][4];
#pragma unroll
    for (int i = 0; i < 4; i++)
#pragma unroll
        for (int j = 0; j < 4; j++)
#pragma unroll
            for (int r = 0; r < 4; r++) acc[i][j][r] = 0.f;

    const int nCh = Kp >> 5;
    for (int kc = 0; kc < nCh; kc++) {
        int k0 = kc << 5;
        load_tile32(sAhi, Ahi, rowBase, M, Kp, k0, tid);
        load_tile32(sAlo, Alo, rowBase, M, Kp, k0, tid);
        load_tile32(sBhi, Bhi, colBase, Nc, Kp, k0, tid);
        load_tile32(sBlo, Blo, colBase, Nc, Kp, k0, tid);
        __syncthreads();
        gemm_pass(uAhi, uBhi, acc, mBase, nBase, laneRow, laneK8);
        gemm_pass(uAhi, uBlo, acc, mBase, nBase, laneRow, laneK8);
        gemm_pass(uAlo, uBhi, acc, mBase, nBase, laneRow, laneK8);
        __syncthreads();
    }

    // epilogue: c0,c1 -> (row g, col 2t/2t+1); c2,c3 -> (row g+8)
    const int g = lane >> 2;
    const int tq = lane & 3;
#pragma unroll
    for (int im = 0; im < 4; im++) {
        int row0 = rowBase + mBase + im * 16 + g;
        int row1 = row0 + 8;
        float rs0 = 1.f, bf0 = 1.f, rs1 = 1.f, bf1 = 1.f;
        if (SCALED) {
            if (row0 < M) { rs0 = rowscale[row0]; bf0 = rs0 > 0.f ? 1.f : 0.f; }
            if (row1 < M) { rs1 = rowscale[row1]; bf1 = rs1 > 0.f ? 1.f : 0.f; }
        }
#pragma unroll
        for (int in8 = 0; in8 < 4; in8++) {
            int col = colBase + nBase + in8 * 8 + tq * 2;
            if (col >= Nc) continue;
            float b0 = bias[col], b1 = bias[col + 1];
            float* cr = acc[im][in8];
            if (row0 < M) {
                float2 o;
                o.x = SCALED ? (rs0 * cr[0] + bf0 * b0) : (cr[0] + b0);
                o.y = SCALED ? (rs0 * cr[1] + bf0 * b1) : (cr[1] + b1);
                *(float2*)(C + (size_t)row0 * Nc + col) = o;
            }
            if (row1 < M) {
                float2 o;
                o.x = SCALED ? (rs1 * cr[2] + bf1 * b0) : (cr[2] + b0);
                o.y = SCALED ? (rs1 * cr[3] + bf1 * b1) : (cr[3] + b1);
                *(float2*)(C + (size_t)row1 * Nc + col) = o;
            }
        }
    }
}

// ---------------- edge aggregation: out[v] = split(sum_e relu(P[v] + Q[src_e])) ----------------
__global__ void edge_agg_split_kernel(const float* __restrict__ PQ, const int* __restrict__ offs,
                                      const int* __restrict__ csr,
                                      __nv_bfloat16* __restrict__ hi,
                                      __nv_bfloat16* __restrict__ lo, int hid) {
    __shared__ int ssrc[1024];
    int v = blockIdx.x;
    int beg = offs[v];
    int end = offs[v + 1];
    int deg = end - beg;
    int tid = threadIdx.x;
    int cached = deg < 1024 ? deg : 1024;
    for (int e = tid; e < cached; e += blockDim.x) ssrc[e] = csr[beg + e];
    __syncthreads();
    const float* Prow = PQ + (size_t)v * (2 * hid);
    size_t obase = (size_t)v * hid;
    for (int c = tid; c < hid; c += blockDim.x) {
        float p = Prow[c];
        float a = 0.f;
        for (int e = 0; e < deg; e++) {
            int s = (e < 1024) ? ssrc[e] : csr[beg + e];
            float t2 = p + PQ[(size_t)s * (2 * hid) + hid + c];
            a += t2 > 0.f ? t2 : 0.f;
        }
        split_write(a, hi, lo, obase + c);
    }
}

// ---------------- BatchNorm ----------------
__global__ void bn_stats_kernel(const float* __restrict__ X, float* __restrict__ stat,
                                int N, int F) {
    int tid = threadIdx.x;
    int c0 = tid, c1 = tid + 256;
    float s0 = 0.f, s1 = 0.f, q0 = 0.f, q1 = 0.f;
    for (int row = blockIdx.x; row < N; row += gridDim.x) {
        const float* r = X + (size_t)row * F;
        if (c0 < F) { float v = r[c0]; s0 += v; q0 += v * v; }
        if (c1 < F) { float v = r[c1]; s1 += v; q1 += v * v; }
    }
    if (c0 < F) { atomicAdd(&stat[c0], s0); atomicAdd(&stat[F + c0], q0); }
    if (c1 < F) { atomicAdd(&stat[c1], s1); atomicAdd(&stat[F + c1], q1); }
}

__global__ void bn_apply_kernel(const float* __restrict__ X, const float* __restrict__ stat,
                                const float* __restrict__ gamma, const float* __restrict__ beta,
                                float* __restrict__ Y, int N, int F) {
    size_t t = (size_t)blockIdx.x * blockDim.x + threadIdx.x;
    size_t n = (size_t)N * F;
    if (t >= n) return;
    int c = (int)(t % F);
    float invN = 1.f / (float)N;
    float mu = stat[c] * invN;
    float var = stat[F + c] * invN - mu * mu;
    float sc = rsqrtf(var + EPS) * gamma[c];
    float y = (X[t] - mu) * sc + beta[c];
    Y[t] = y > 0.f ? y : 0.f;
}

// ---------------- distribute_features ----------------
__global__ void dist_scatter_kernel(const float* __restrict__ feat, const int* __restrict__ idx,
                                    float* __restrict__ vsum, int n3, int F3) {
    size_t t = (size_t)blockIdx.x * blockDim.x + threadIdx.x;
    size_t n = (size_t)n3 * F3;
    if (t >= n) return;
    int r = (int)(t / F3);
    int c = (int)(t % F3);
    atomicAdd(&vsum[(size_t)idx[r] * F3 + c], feat[t]);
}

__global__ void dist_gather_split_kernel(const float* __restrict__ vsum, const int* __restrict__ vcnt,
                                         const int* __restrict__ idx,
                                         __nv_bfloat16* __restrict__ hi,
                                         __nv_bfloat16* __restrict__ lo, int n3, int F3, int stride) {
    size_t t = (size_t)blockIdx.x * blockDim.x + threadIdx.x;
    size_t n = (size_t)n3 * F3;
    if (t >= n) return;
    int r = (int)(t / F3);
    int c = (int)(t % F3);
    int v = idx[r];
    float cn = (float)vcnt[v];
    float val = vsum[(size_t)v * F3 + c] / (cn > 0.f ? cn : 1.f);
    int node = r / 3;
    int col = (r % 3) * F3 + c;
    split_write(val, hi, lo, (size_t)node * stride + col);
}

__global__ void dist_gather_f32_kernel(const float* __restrict__ vsum, const int* __restrict__ vcnt,
                                       const int* __restrict__ idx, float* __restrict__ out,
                                       int n3, int F3) {
    size_t t = (size_t)blockIdx.x * blockDim.x + threadIdx.x;
    size_t n = (size_t)n3 * F3;
    if (t >= n) return;
    int r = (int)(t / F3);
    int c = (int)(t % F3);
    int v = idx[r];
    float cn = (float)vcnt[v];
    out[t] = vsum[(size_t)v * F3 + c] / (cn > 0.f ? cn : 1.f);
}

// ---------------- host ----------------
static inline int ceil_div(long long a, int b) { return (int)((a + b - 1) / b); }

extern "C" void kernel_launch(void* const* d_in, const int* in_sizes, int n_in,
                              void* d_out, int out_size) {
    const float* x     = (const float*)d_in[0];
    const int*   ei    = (const int*)d_in[1];
    const int*   faces = (const int*)d_in[2];
    int argbase = (n_in >= 32) ? 4 : 3;

    int N = in_sizes[0] / 16;
    int E = in_sizes[1] / 2;
    int n3 = N * 3;

    float *H, *PQ, *U, *bc, *vsum, *stat, *rscale;
    __nv_bfloat16 *Ahi, *Alo, *Bhi, *Blo;
    int *deg, *offs, *cur, *csr, *vcnt;
    cudaGetSymbolAddress((void**)&H, g_H);
    cudaGetSymbolAddress((void**)&PQ, g_PQ);
    cudaGetSymbolAddress((void**)&U, g_U);
    cudaGetSymbolAddress((void**)&Ahi, g_Ahi);
    cudaGetSymbolAddress((void**)&Alo, g_Alo);
    cudaGetSymbolAddress((void**)&Bhi, g_Bhi);
    cudaGetSymbolAddress((void**)&Blo, g_Blo);
    cudaGetSymbolAddress((void**)&bc, g_bc);
    cudaGetSymbolAddress((void**)&vsum, g_vsum);
    cudaGetSymbolAddress((void**)&stat, g_stat);
    cudaGetSymbolAddress((void**)&rscale, g_rscale);
    cudaGetSymbolAddress((void**)&deg, g_deg);
    cudaGetSymbolAddress((void**)&offs, g_offs);
    cudaGetSymbolAddress((void**)&cur, g_cur);
    cudaGetSymbolAddress((void**)&csr, g_csr);
    cudaGetSymbolAddress((void**)&vcnt, g_vcnt);

    // CSR (by dst) + vertex counts
    zero_i_kernel<<<ceil_div(N, 256), 256>>>(deg, N);
    count_deg_kernel<<<ceil_div(E, 256), 256>>>(ei, deg, E);
    scan_kernel<<<1, 1024>>>(deg, offs, cur, rscale, N);
    fill_csr_kernel<<<ceil_div(E, 256), 256>>>(ei, cur, csr, E);
    zero_i_kernel<<<ceil_div(VMAX, 256), 256>>>(vcnt, VMAX);
    vcnt_kernel<<<ceil_div(n3, 256), 256>>>(faces, vcnt, n3);

    // embedding -> split bf16 [N,256]
    embed_split_kernel<<<ceil_div(N, 128), 128>>>(x, Ahi, Alo, N);

    struct LCfg { int F, hid, out; };
    const LCfg ls[5] = {
        {196, 192, 96}, {96, 384, 192}, {192, 768, 384}, {384, 768, 384}, {384, 1152, 576}
    };

    int rowT = ceil_div(N, 128);
    for (int L = 0; L < 5; L++) {
        const LCfg& cf = ls[L];
        const float* w1 = (const float*)d_in[argbase + 4 * L + 0];
        const float* b1 = (const float*)d_in[argbase + 4 * L + 1];
        const float* w2 = (const float*)d_in[argbase + 4 * L + 2];
        const float* b2 = (const float*)d_in[argbase + 4 * L + 3];

        int Kp1 = ((cf.F + 63) / 64) * 64;     // 256,128,192,384,384
        int Nc1 = 2 * cf.hid;                  // 384..2304 (all /128)

        prep_w_split_kernel<<<ceil_div((long long)Nc1 * Kp1, 256), 256>>>(w1, Bhi, Blo, cf.F, cf.hid, Kp1);
        prep_b_kernel<<<ceil_div(Nc1, 256), 256>>>(b1, bc, cf.hid);

        // PQ = A @ B1 + bc   [N, 2*hid]
        gemm_mma<false><<<dim3(Nc1 / 128, rowT), 256>>>(
            Ahi, Alo, Bhi, Blo, PQ, N, Kp1, Nc1, bc, nullptr);

        // T[v] = split(sum_e relu(P[v] + Q[src]))  -> Ahi/Alo [N, hid]
        edge_agg_split_kernel<<<N, 128>>>(PQ, offs, csr, Ahi, Alo, cf.hid);

        prep_w2t_split_kernel<<<ceil_div((long long)cf.out * cf.hid, 256), 256>>>(
            w2, Bhi, Blo, cf.hid, cf.out, cf.hid);

        // U = rowscale * (T @ w2) + (deg>0)*b2   [N, out]
        gemm_mma<true><<<dim3(ceil_div(cf.out, 128), rowT), 256>>>(
            Ahi, Alo, Bhi, Blo, U, N, cf.hid, cf.out, b2, rscale);

        int F3 = cf.out / 3;
        zero_f_kernel<<<ceil_div((long long)VMAX * F3, 256), 256>>>(vsum, (size_t)VMAX * F3);
        if (L < 4) {
            const float* gamma = (const float*)d_in[argbase + 20 + 2 * L];
            const float* beta  = (const float*)d_in[argbase + 20 + 2 * L + 1];
            zero_f_kernel<<<ceil_div(2 * cf.out, 256), 256>>>(stat, 2 * cf.out);
            bn_stats_kernel<<<512, 256>>>(U, stat, N, cf.out);
            bn_apply_kernel<<<ceil_div((long long)N * cf.out, 256), 256>>>(
                U, stat, gamma, beta, H, N, cf.out);
            dist_scatter_kernel<<<ceil_div((long long)n3 * F3, 256), 256>>>(H, faces, vsum, n3, F3);
            int KpNext = ((cf.out + 63) / 64) * 64;
            dist_gather_split_kernel<<<ceil_div((long long)n3 * F3, 256), 256>>>(
                vsum, vcnt, faces, Ahi, Alo, n3, F3, KpNext);
            if (KpNext > cf.out) {
                pad_split_kernel<<<ceil_div((long long)N * (KpNext - cf.out), 256), 256>>>(
                    Ahi, Alo, N, cf.out, KpNext);
            }
        } else {
            dist_scatter_kernel<<<ceil_div((long long)n3 * F3, 256), 256>>>(U, faces, vsum, n3, F3);
            dist_gather_f32_kernel<<<ceil_div((long long)n3 * F3, 256), 256>>>(
                vsum, vcnt, faces, (float*)d_out, n3, F3);
        }
    }
}

// round 8
// speedup vs baseline: 1.4718x; 1.2899x over previous
#include <cuda_runtime.h>
#include <cuda_bf16.h>
#include <cstdint>
#include <cstddef>

#define NMAX   100000
#define EMAX   300000
#define VMAX   50000
#define HMAX   1152
#define OUTMAX 576
#define EPS    1e-5f

// ---------------- static scratch ----------------
__device__ float g_H [(size_t)NMAX * OUTMAX];
__device__ float g_PQ[(size_t)NMAX * 2 * HMAX];
__device__ float g_U [(size_t)NMAX * OUTMAX];
__device__ __nv_bfloat16 g_Ahi[(size_t)NMAX * HMAX];
__device__ __nv_bfloat16 g_Alo[(size_t)NMAX * HMAX];
__device__ __nv_bfloat16 g_Bhi[1048576];
__device__ __nv_bfloat16 g_Blo[1048576];
__device__ float g_bc[2 * HMAX];
__device__ float g_vsum[(size_t)VMAX * (OUTMAX / 3)];
__device__ float g_stat[2 * OUTMAX];
__device__ float g_rscale[NMAX];
__device__ int   g_deg[NMAX];
__device__ int   g_offs[NMAX + 1];
__device__ int   g_cur[NMAX];
__device__ int   g_csr[EMAX];
__device__ int   g_vcnt[VMAX];

// ---------------- helpers ----------------
__device__ __forceinline__ uint32_t smem_u32(const void* p) {
    uint32_t a;
    asm("{ .reg .u64 t; cvta.to.shared.u64 t, %1; cvt.u32.u64 %0, t; }" : "=r"(a) : "l"(p));
    return a;
}
__device__ __forceinline__ void mma_bf16(float* c, const uint32_t* a, uint32_t b0, uint32_t b1) {
    asm volatile(
        "mma.sync.aligned.m16n8k16.row.col.f32.bf16.bf16.f32 "
        "{%0,%1,%2,%3}, {%4,%5,%6,%7}, {%8,%9}, {%0,%1,%2,%3};"
        : "+f"(c[0]), "+f"(c[1]), "+f"(c[2]), "+f"(c[3])
        : "r"(a[0]), "r"(a[1]), "r"(a[2]), "r"(a[3]), "r"(b0), "r"(b1));
}
__device__ __forceinline__ void ldm4(uint32_t* r, uint32_t addr) {
    asm volatile("ldmatrix.sync.aligned.m8n8.x4.shared.b16 {%0,%1,%2,%3}, [%4];"
                 : "=r"(r[0]), "=r"(r[1]), "=r"(r[2]), "=r"(r[3]) : "r"(addr));
}
__device__ __forceinline__ void cpa16(uint32_t dst, const __nv_bfloat16* src, bool valid) {
    int sz = valid ? 16 : 0;
    asm volatile("cp.async.cg.shared.global [%0], [%1], 16, %2;" :: "r"(dst), "l"(src), "r"(sz));
}
#define CP_COMMIT() asm volatile("cp.async.commit_group;" ::: "memory")
#define CP_WAIT(n)  asm volatile("cp.async.wait_group %0;" :: "n"(n) : "memory")

__device__ __forceinline__ void split_write(float v, __nv_bfloat16* hi, __nv_bfloat16* lo, size_t i) {
    __nv_bfloat16 h = __float2bfloat16(v);
    hi[i] = h;
    lo[i] = __float2bfloat16(v - __bfloat162float(h));
}

// ---------------- utility kernels ----------------
__global__ void zero_f_kernel(float* p, size_t n) {
    size_t i = (size_t)blockIdx.x * blockDim.x + threadIdx.x;
    if (i < n) p[i] = 0.f;
}
__global__ void zero_i_kernel(int* p, int n) {
    int i = blockIdx.x * blockDim.x + threadIdx.x;
    if (i < n) p[i] = 0;
}
__global__ void pad_split_kernel(__nv_bfloat16* hi, __nv_bfloat16* lo, int N, int F, int stride) {
    int padw = stride - F;
    int t = blockIdx.x * blockDim.x + threadIdx.x;
    int n = N * padw;
    if (t >= n) return;
    int node = t / padw;
    int c = F + (t % padw);
    size_t i = (size_t)node * stride + c;
    hi[i] = __float2bfloat16(0.f);
    lo[i] = __float2bfloat16(0.f);
}

// ---------------- embed -> split bf16 [N x 256] ----------------
__global__ void embed_split_kernel(const float* __restrict__ x,
                                   __nv_bfloat16* __restrict__ hi,
                                   __nv_bfloat16* __restrict__ lo, int N) {
    int n = blockIdx.x * blockDim.x + threadIdx.x;
    if (n >= N) return;
    const float* xr = x + (size_t)n * 16;
    size_t base = (size_t)n * 256;
#pragma unroll
    for (int g = 0; g < 3; g++) {
        const float* p = xr + g * 3;
        size_t o = base + g * 63;
        split_write(p[0], hi, lo, o + 0);
        split_write(p[1], hi, lo, o + 1);
        split_write(p[2], hi, lo, o + 2);
#pragma unroll
        for (int c = 0; c < 3; c++) {
            float f = 1.f;
#pragma unroll
            for (int q = 0; q < 10; q++) {
                float ang = p[c] * f;
                split_write(sinf(ang), hi, lo, o + 3 + c * 20 + q * 2);
                split_write(cosf(ang), hi, lo, o + 3 + c * 20 + q * 2 + 1);
                f *= 2.f;
            }
        }
    }
#pragma unroll
    for (int k = 0; k < 7; k++) split_write(xr[9 + k], hi, lo, base + 189 + k);
#pragma unroll
    for (int k = 196; k < 256; k++) { hi[base + k] = __float2bfloat16(0.f); lo[base + k] = __float2bfloat16(0.f); }
}

// ---------------- CSR build ----------------
__global__ void count_deg_kernel(const int* __restrict__ ei, int* __restrict__ deg, int E) {
    int e = blockIdx.x * blockDim.x + threadIdx.x;
    if (e < E) atomicAdd(&deg[ei[E + e]], 1);
}

__global__ void scan_kernel(const int* __restrict__ deg, int* __restrict__ offs,
                            int* __restrict__ cur, float* __restrict__ rscale, int N) {
    __shared__ int part[1024];
    int t = threadIdx.x;
    int chunk = (N + 1023) >> 10;
    int lo = t * chunk;
    int hi = lo + chunk; if (hi > N) hi = N;
    if (lo > N) lo = N;
    int s = 0;
    for (int i = lo; i < hi; i++) s += deg[i];
    part[t] = s;
    __syncthreads();
    for (int off = 1; off < 1024; off <<= 1) {
        int v = (t >= off) ? part[t - off] : 0;
        __syncthreads();
        part[t] += v;
        __syncthreads();
    }
    int base = (t == 0) ? 0 : part[t - 1];
    for (int i = lo; i < hi; i++) {
        offs[i] = base;
        cur[i] = base;
        int d = deg[i];
        rscale[i] = d > 0 ? 1.f / (float)d : 0.f;
        base += d;
    }
    if (t == 1023) offs[N] = part[1023];
}

__global__ void fill_csr_kernel(const int* __restrict__ ei, int* __restrict__ cur,
                                int* __restrict__ csr, int E) {
    int e = blockIdx.x * blockDim.x + threadIdx.x;
    if (e < E) {
        int d = ei[E + e];
        int pos = atomicAdd(&cur[d], 1);
        csr[pos] = ei[e];
    }
}

__global__ void vcnt_kernel(const int* __restrict__ faces, int* __restrict__ vcnt, int n3) {
    int t = blockIdx.x * blockDim.x + threadIdx.x;
    if (t < n3) atomicAdd(&vcnt[faces[t]], 1);
}

// ---------------- weight prep ----------------
__global__ void prep_w_split_kernel(const float* __restrict__ w1,
                                    __nv_bfloat16* __restrict__ hi,
                                    __nv_bfloat16* __restrict__ lo,
                                    int F, int hid, int Kp) {
    int t = blockIdx.x * blockDim.x + threadIdx.x;
    int n = 2 * hid * Kp;
    if (t >= n) return;
    int j = t / Kp;
    int k = t % Kp;
    float v = 0.f;
    if (k < F) {
        if (j < hid) v = w1[(size_t)k * hid + j] - w1[(size_t)(F + k) * hid + j];
        else         v = w1[(size_t)(F + k) * hid + (j - hid)];
    }
    split_write(v, hi, lo, t);
}
__global__ void prep_w2t_split_kernel(const float* __restrict__ w2,
                                      __nv_bfloat16* __restrict__ hi,
                                      __nv_bfloat16* __restrict__ lo,
                                      int hid, int out, int Kp) {
    int t = blockIdx.x * blockDim.x + threadIdx.x;
    int n = out * Kp;
    if (t >= n) return;
    int j = t / Kp;
    int k = t % Kp;
    float v = (k < hid) ? w2[(size_t)k * out + j] : 0.f;
    split_write(v, hi, lo, t);
}
__global__ void prep_b_kernel(const float* __restrict__ b1, float* __restrict__ bc, int hid) {
    int j = blockIdx.x * blockDim.x + threadIdx.x;
    if (j < 2 * hid) bc[j] = (j < hid) ? b1[j] : 0.f;
}

// ---------------- mma.sync split-bf16 GEMM (fused 3-term, cp.async double-buffer) ----------------
// C[M,Nc] = (Ahi+Alo)[M,Kp] @ (Bhi+Blo)^T[Kp,Nc]   (B stored [Nc][Kp], K-major)
// CTA 128x128, BK=32, 8 warps (2x4), warp tile 64x32, smem pitch 40 bf16.
#define SPITCH 40
#define TILE_B  (128 * SPITCH * 2)          // 10240 bytes per tile
#define STAGE_B (4 * TILE_B)                // 40960 bytes per stage
#define SMEM_GEMM (2 * STAGE_B)             // 81920 bytes

__device__ __forceinline__ void issue_stage(uint32_t sbase,
                                            const __nv_bfloat16* __restrict__ Ahi,
                                            const __nv_bfloat16* __restrict__ Alo,
                                            const __nv_bfloat16* __restrict__ Bhi,
                                            const __nv_bfloat16* __restrict__ Blo,
                                            int rowBase, int M, int colBase, int Nc,
                                            int Kp, int k0, int tid) {
#pragma unroll
    for (int i = 0; i < 2; i++) {
        int idx = tid + (i << 8);           // 0..511
        int r = idx >> 2;
        int c8 = (idx & 3) << 3;
        uint32_t off = (uint32_t)((r * SPITCH + c8) * 2);
        size_t gofsA = (size_t)(rowBase + r) * Kp + k0 + c8;
        size_t gofsB = (size_t)(colBase + r) * Kp + k0 + c8;
        bool va = (rowBase + r) < M;
        bool vb = (colBase + r) < Nc;
        cpa16(sbase + off,              Ahi + gofsA, va);
        cpa16(sbase + TILE_B + off,     Alo + gofsA, va);
        cpa16(sbase + 2 * TILE_B + off, Bhi + gofsB, vb);
        cpa16(sbase + 3 * TILE_B + off, Blo + gofsB, vb);
    }
}

template <bool SCALED>
__global__ void __launch_bounds__(256, 2)
gemm_mma(const __nv_bfloat16* __restrict__ Ahi, const __nv_bfloat16* __restrict__ Alo,
         const __nv_bfloat16* __restrict__ Bhi, const __nv_bfloat16* __restrict__ Blo,
         float* __restrict__ C, int M, int Kp, int Nc,
         const float* __restrict__ bias, const float* __restrict__ rowscale) {
    extern __shared__ __align__(16) char smem[];
    const int tid = threadIdx.x;
    const int wid = tid >> 5;
    const int lane = tid & 31;
    const int colBase = blockIdx.x << 7;
    const int rowBase = blockIdx.y << 7;
    const int mBase = (wid >> 2) * 64;
    const int nBase = (wid & 3) * 32;
    const int laneRow = lane & 15;
    const int laneK8 = (lane >> 4) << 3;

    uint32_t sb = smem_u32(smem);

    float acc[4][4][4];
#pragma unroll
    for (int i = 0; i < 4; i++)
#pragma unroll
        for (int j = 0; j < 4; j++)
#pragma unroll
            for (int r = 0; r < 4; r++) acc[i][j][r] = 0.f;

    const int nCh = Kp >> 5;
    issue_stage(sb, Ahi, Alo, Bhi, Blo, rowBase, M, colBase, Nc, Kp, 0, tid);
    CP_COMMIT();

    for (int kc = 0; kc < nCh; kc++) {
        uint32_t st = sb + (uint32_t)(kc & 1) * STAGE_B;
        if (kc + 1 < nCh) {
            issue_stage(sb + (uint32_t)((kc + 1) & 1) * STAGE_B,
                        Ahi, Alo, Bhi, Blo, rowBase, M, colBase, Nc, Kp, (kc + 1) << 5, tid);
            CP_COMMIT();
            CP_WAIT(1);
        } else {
            CP_WAIT(0);
        }
        __syncthreads();

        uint32_t uAhi = st;
        uint32_t uAlo = st + TILE_B;
        uint32_t uBhi = st + 2 * TILE_B;
        uint32_t uBlo = st + 3 * TILE_B;

#pragma unroll
        for (int k16 = 0; k16 < 32; k16 += 16) {
            uint32_t bhi[2][4], blo[2][4];
#pragma unroll
            for (int in2 = 0; in2 < 2; in2++) {
                uint32_t boff = (uint32_t)(((nBase + in2 * 16 + laneRow) * SPITCH + k16 + laneK8) * 2);
                ldm4(bhi[in2], uBhi + boff);
                ldm4(blo[in2], uBlo + boff);
            }
#pragma unroll
            for (int im = 0; im < 4; im++) {
                uint32_t aoff = (uint32_t)(((mBase + im * 16 + laneRow) * SPITCH + k16 + laneK8) * 2);
                uint32_t a[4];
                ldm4(a, uAhi + aoff);
#pragma unroll
                for (int in2 = 0; in2 < 2; in2++) {
                    mma_bf16(acc[im][in2 * 2 + 0], a, bhi[in2][0], bhi[in2][2]);
                    mma_bf16(acc[im][in2 * 2 + 1], a, bhi[in2][1], bhi[in2][3]);
                    mma_bf16(acc[im][in2 * 2 + 0], a, blo[in2][0], blo[in2][2]);
                    mma_bf16(acc[im][in2 * 2 + 1], a, blo[in2][1], blo[in2][3]);
                }
                ldm4(a, uAlo + aoff);
#pragma unroll
                for (int in2 = 0; in2 < 2; in2++) {
                    mma_bf16(acc[im][in2 * 2 + 0], a, bhi[in2][0], bhi[in2][2]);
                    mma_bf16(acc[im][in2 * 2 + 1], a, bhi[in2][1], bhi[in2][3]);
                }
            }
        }
        __syncthreads();
    }

    // epilogue
    const int g = lane >> 2;
    const int tq = lane & 3;
#pragma unroll
    for (int im = 0; im < 4; im++) {
        int row0 = rowBase + mBase + im * 16 + g;
        int row1 = row0 + 8;
        float rs0 = 1.f, bf0 = 1.f, rs1 = 1.f, bf1 = 1.f;
        if (SCALED) {
            if (row0 < M) { rs0 = rowscale[row0]; bf0 = rs0 > 0.f ? 1.f : 0.f; }
            if (row1 < M) { rs1 = rowscale[row1]; bf1 = rs1 > 0.f ? 1.f : 0.f; }
        }
#pragma unroll
        for (int in8 = 0; in8 < 4; in8++) {
            int col = colBase + nBase + in8 * 8 + tq * 2;
            if (col >= Nc) continue;
            float b0 = bias[col], b1 = bias[col + 1];
            float* cr = acc[im][in8];
            if (row0 < M) {
                float2 o;
                o.x = SCALED ? (rs0 * cr[0] + bf0 * b0) : (cr[0] + b0);
                o.y = SCALED ? (rs0 * cr[1] + bf0 * b1) : (cr[1] + b1);
                *(float2*)(C + (size_t)row0 * Nc + col) = o;
            }
            if (row1 < M) {
                float2 o;
                o.x = SCALED ? (rs1 * cr[2] + bf1 * b0) : (cr[2] + b0);
                o.y = SCALED ? (rs1 * cr[3] + bf1 * b1) : (cr[3] + b1);
                *(float2*)(C + (size_t)row1 * Nc + col) = o;
            }
        }
    }
}

// ---------------- edge aggregation ----------------
__global__ void edge_agg_split_kernel(const float* __restrict__ PQ, const int* __restrict__ offs,
                                      const int* __restrict__ csr,
                                      __nv_bfloat16* __restrict__ hi,
                                      __nv_bfloat16* __restrict__ lo, int hid) {
    __shared__ int ssrc[1024];
    int v = blockIdx.x;
    int beg = offs[v];
    int end = offs[v + 1];
    int deg = end - beg;
    int tid = threadIdx.x;
    int cached = deg < 1024 ? deg : 1024;
    for (int e = tid; e < cached; e += blockDim.x) ssrc[e] = csr[beg + e];
    __syncthreads();
    const float* Prow = PQ + (size_t)v * (2 * hid);
    size_t obase = (size_t)v * hid;
    for (int c = tid; c < hid; c += blockDim.x) {
        float p = Prow[c];
        float a = 0.f;
        for (int e = 0; e < deg; e++) {
            int s = (e < 1024) ? ssrc[e] : csr[beg + e];
            float t2 = p + PQ[(size_t)s * (2 * hid) + hid + c];
            a += t2 > 0.f ? t2 : 0.f;
        }
        split_write(a, hi, lo, obase + c);
    }
}

// ---------------- BatchNorm ----------------
__global__ void bn_stats_kernel(const float* __restrict__ X, float* __restrict__ stat,
                                int N, int F) {
    int tid = threadIdx.x;
    int c0 = tid, c1 = tid + 256;
    float s0 = 0.f, s1 = 0.f, q0 = 0.f, q1 = 0.f;
    for (int row = blockIdx.x; row < N; row += gridDim.x) {
        const float* r = X + (size_t)row * F;
        if (c0 < F) { float v = r[c0]; s0 += v; q0 += v * v; }
        if (c1 < F) { float v = r[c1]; s1 += v; q1 += v * v; }
    }
    if (c0 < F) { atomicAdd(&stat[c0], s0); atomicAdd(&stat[F + c0], q0); }
    if (c1 < F) { atomicAdd(&stat[c1], s1); atomicAdd(&stat[F + c1], q1); }
}

__global__ void bn_apply_kernel(const float* __restrict__ X, const float* __restrict__ stat,
                                const float* __restrict__ gamma, const float* __restrict__ beta,
                                float* __restrict__ Y, int N, int F) {
    size_t t = (size_t)blockIdx.x * blockDim.x + threadIdx.x;
    size_t n = (size_t)N * F;
    if (t >= n) return;
    int c = (int)(t % F);
    float invN = 1.f / (float)N;
    float mu = stat[c] * invN;
    float var = stat[F + c] * invN - mu * mu;
    float sc = rsqrtf(var + EPS) * gamma[c];
    float y = (X[t] - mu) * sc + beta[c];
    Y[t] = y > 0.f ? y : 0.f;
}

// ---------------- distribute_features ----------------
__global__ void dist_scatter_kernel(const float* __restrict__ feat, const int* __restrict__ idx,
                                    float* __restrict__ vsum, int n3, int F3) {
    size_t t = (size_t)blockIdx.x * blockDim.x + threadIdx.x;
    size_t n = (size_t)n3 * F3;
    if (t >= n) return;
    int r = (int)(t / F3);
    int c = (int)(t % F3);
    atomicAdd(&vsum[(size_t)idx[r] * F3 + c], feat[t]);
}

__global__ void dist_gather_split_kernel(const float* __restrict__ vsum, const int* __restrict__ vcnt,
                                         const int* __restrict__ idx,
                                         __nv_bfloat16* __restrict__ hi,
                                         __nv_bfloat16* __restrict__ lo, int n3, int F3, int stride) {
    size_t t = (size_t)blockIdx.x * blockDim.x + threadIdx.x;
    size_t n = (size_t)n3 * F3;
    if (t >= n) return;
    int r = (int)(t / F3);
    int c = (int)(t % F3);
    int v = idx[r];
    float cn = (float)vcnt[v];
    float val = vsum[(size_t)v * F3 + c] / (cn > 0.f ? cn : 1.f);
    int node = r / 3;
    int col = (r % 3) * F3 + c;
    split_write(val, hi, lo, (size_t)node * stride + col);
}

__global__ void dist_gather_f32_kernel(const float* __restrict__ vsum, const int* __restrict__ vcnt,
                                       const int* __restrict__ idx, float* __restrict__ out,
                                       int n3, int F3) {
    size_t t = (size_t)blockIdx.x * blockDim.x + threadIdx.x;
    size_t n = (size_t)n3 * F3;
    if (t >= n) return;
    int r = (int)(t / F3);
    int c = (int)(t % F3);
    int v = idx[r];
    float cn = (float)vcnt[v];
    out[t] = vsum[(size_t)v * F3 + c] / (cn > 0.f ? cn : 1.f);
}

// ---------------- host ----------------
static inline int ceil_div(long long a, int b) { return (int)((a + b - 1) / b); }

extern "C" void kernel_launch(void* const* d_in, const int* in_sizes, int n_in,
                              void* d_out, int out_size) {
    const float* x     = (const float*)d_in[0];
    const int*   ei    = (const int*)d_in[1];
    const int*   faces = (const int*)d_in[2];
    int argbase = (n_in >= 32) ? 4 : 3;

    int N = in_sizes[0] / 16;
    int E = in_sizes[1] / 2;
    int n3 = N * 3;

    float *H, *PQ, *U, *bc, *vsum, *stat, *rscale;
    __nv_bfloat16 *Ahi, *Alo, *Bhi, *Blo;
    int *deg, *offs, *cur, *csr, *vcnt;
    cudaGetSymbolAddress((void**)&H, g_H);
    cudaGetSymbolAddress((void**)&PQ, g_PQ);
    cudaGetSymbolAddress((void**)&U, g_U);
    cudaGetSymbolAddress((void**)&Ahi, g_Ahi);
    cudaGetSymbolAddress((void**)&Alo, g_Alo);
    cudaGetSymbolAddress((void**)&Bhi, g_Bhi);
    cudaGetSymbolAddress((void**)&Blo, g_Blo);
    cudaGetSymbolAddress((void**)&bc, g_bc);
    cudaGetSymbolAddress((void**)&vsum, g_vsum);
    cudaGetSymbolAddress((void**)&stat, g_stat);
    cudaGetSymbolAddress((void**)&rscale, g_rscale);
    cudaGetSymbolAddress((void**)&deg, g_deg);
    cudaGetSymbolAddress((void**)&offs, g_offs);
    cudaGetSymbolAddress((void**)&cur, g_cur);
    cudaGetSymbolAddress((void**)&csr, g_csr);
    cudaGetSymbolAddress((void**)&vcnt, g_vcnt);

    cudaFuncSetAttribute(gemm_mma<false>, cudaFuncAttributeMaxDynamicSharedMemorySize, SMEM_GEMM);
    cudaFuncSetAttribute(gemm_mma<true>,  cudaFuncAttributeMaxDynamicSharedMemorySize, SMEM_GEMM);

    struct LCfg { int F, hid, out; };
    const LCfg ls[5] = {
        {196, 192, 96}, {96, 384, 192}, {192, 768, 384}, {384, 768, 384}, {384, 1152, 576}
    };
    int rowT = ceil_div(N, 128);

    // --- launches 0-5 arranged so ncu (-s 5) captures the layer-1 gemm ---
    zero_i_kernel<<<ceil_div(N, 256), 256>>>(deg, N);                       // 0
    count_deg_kernel<<<ceil_div(E, 256), 256>>>(ei, deg, E);                // 1
    embed_split_kernel<<<ceil_div(N, 128), 128>>>(x, Ahi, Alo, N);          // 2
    {
        const LCfg& cf = ls[0];
        const float* w1 = (const float*)d_in[argbase + 0];
        const float* b1 = (const float*)d_in[argbase + 1];
        int Kp1 = 256, Nc1 = 2 * cf.hid;
        prep_w_split_kernel<<<ceil_div((long long)Nc1 * Kp1, 256), 256>>>(w1, Bhi, Blo, cf.F, cf.hid, Kp1); // 3
        prep_b_kernel<<<ceil_div(Nc1, 256), 256>>>(b1, bc, cf.hid);         // 4
        gemm_mma<false><<<dim3(Nc1 / 128, rowT), 256, SMEM_GEMM>>>(         // 5  <- profiled
            Ahi, Alo, Bhi, Blo, PQ, N, Kp1, Nc1, bc, nullptr);
    }
    // remaining CSR/vcnt setup (needed before edge_agg / dist)
    scan_kernel<<<1, 1024>>>(deg, offs, cur, rscale, N);
    fill_csr_kernel<<<ceil_div(E, 256), 256>>>(ei, cur, csr, E);
    zero_i_kernel<<<ceil_div(VMAX, 256), 256>>>(vcnt, VMAX);
    vcnt_kernel<<<ceil_div(n3, 256), 256>>>(faces, vcnt, n3);

    for (int L = 0; L < 5; L++) {
        const LCfg& cf = ls[L];
        const float* w1 = (const float*)d_in[argbase + 4 * L + 0];
        const float* b1 = (const float*)d_in[argbase + 4 * L + 1];
        const float* w2 = (const float*)d_in[argbase + 4 * L + 2];
        const float* b2 = (const float*)d_in[argbase + 4 * L + 3];

        int Kp1 = ((cf.F + 63) / 64) * 64;
        int Nc1 = 2 * cf.hid;

        if (L > 0) {  // layer 0's first gemm already launched above
            prep_w_split_kernel<<<ceil_div((long long)Nc1 * Kp1, 256), 256>>>(w1, Bhi, Blo, cf.F, cf.hid, Kp1);
            prep_b_kernel<<<ceil_div(Nc1, 256), 256>>>(b1, bc, cf.hid);
            gemm_mma<false><<<dim3(Nc1 / 128, rowT), 256, SMEM_GEMM>>>(
                Ahi, Alo, Bhi, Blo, PQ, N, Kp1, Nc1, bc, nullptr);
        }

        edge_agg_split_kernel<<<N, 128>>>(PQ, offs, csr, Ahi, Alo, cf.hid);

        prep_w2t_split_kernel<<<ceil_div((long long)cf.out * cf.hid, 256), 256>>>(
            w2, Bhi, Blo, cf.hid, cf.out, cf.hid);

        gemm_mma<true><<<dim3(ceil_div(cf.out, 128), rowT), 256, SMEM_GEMM>>>(
            Ahi, Alo, Bhi, Blo, U, N, cf.hid, cf.out, b2, rscale);

        int F3 = cf.out / 3;
        zero_f_kernel<<<ceil_div((long long)VMAX * F3, 256), 256>>>(vsum, (size_t)VMAX * F3);
        if (L < 4) {
            const float* gamma = (const float*)d_in[argbase + 20 + 2 * L];
            const float* beta  = (const float*)d_in[argbase + 20 + 2 * L + 1];
            zero_f_kernel<<<ceil_div(2 * cf.out, 256), 256>>>(stat, 2 * cf.out);
            bn_stats_kernel<<<512, 256>>>(U, stat, N, cf.out);
            bn_apply_kernel<<<ceil_div((long long)N * cf.out, 256), 256>>>(
                U, stat, gamma, beta, H, N, cf.out);
            dist_scatter_kernel<<<ceil_div((long long)n3 * F3, 256), 256>>>(H, faces, vsum, n3, F3);
            int KpNext = ((cf.out + 63) / 64) * 64;
            dist_gather_split_kernel<<<ceil_div((long long)n3 * F3, 256), 256>>>(
                vsum, vcnt, faces, Ahi, Alo, n3, F3, KpNext);
            if (KpNext > cf.out) {
                pad_split_kernel<<<ceil_div((long long)N * (KpNext - cf.out), 256), 256>>>(
                    Ahi, Alo, N, cf.out, KpNext);
            }
        } else {
            dist_scatter_kernel<<<ceil_div((long long)n3 * F3, 256), 256>>>(U, faces, vsum, n3, F3);
            dist_gather_f32_kernel<<<ceil_div((long long)n3 * F3, 256), 256>>>(
                vsum, vcnt, faces, (float*)d_out, n3, F3);
        }
    }
}

// round 9
// speedup vs baseline: 1.4980x; 1.0179x over previous
#include <cuda_runtime.h>
#include <cuda_bf16.h>
#include <cstdint>
#include <cstddef>

#define NMAX   100000
#define EMAX   300000
#define VMAX   50000
#define HMAX   1152
#define OUTMAX 576
#define EPS    1e-5f

// ---------------- static scratch ----------------
__device__ float g_PQ[(size_t)NMAX * 2 * HMAX];
__device__ float g_U [(size_t)NMAX * OUTMAX];
__device__ __nv_bfloat16 g_Ahi[(size_t)NMAX * HMAX];
__device__ __nv_bfloat16 g_Alo[(size_t)NMAX * HMAX];
__device__ __nv_bfloat16 g_Bhi[1048576];
__device__ __nv_bfloat16 g_Blo[1048576];
__device__ float g_bc[2 * HMAX];
__device__ float g_vsum[(size_t)VMAX * (OUTMAX / 3)];
__device__ float g_stat[2 * OUTMAX];
__device__ float g_rscale[NMAX];
__device__ int   g_deg[NMAX];
__device__ int   g_offs[NMAX + 1];
__device__ int   g_cur[NMAX];
__device__ int   g_csr[EMAX];
__device__ int   g_vcnt[VMAX];

// ---------------- helpers ----------------
__device__ __forceinline__ uint32_t smem_u32(const void* p) {
    uint32_t a;
    asm("{ .reg .u64 t; cvta.to.shared.u64 t, %1; cvt.u32.u64 %0, t; }" : "=r"(a) : "l"(p));
    return a;
}
__device__ __forceinline__ void mma_bf16(float* c, const uint32_t* a, uint32_t b0, uint32_t b1) {
    asm volatile(
        "mma.sync.aligned.m16n8k16.row.col.f32.bf16.bf16.f32 "
        "{%0,%1,%2,%3}, {%4,%5,%6,%7}, {%8,%9}, {%0,%1,%2,%3};"
        : "+f"(c[0]), "+f"(c[1]), "+f"(c[2]), "+f"(c[3])
        : "r"(a[0]), "r"(a[1]), "r"(a[2]), "r"(a[3]), "r"(b0), "r"(b1));
}
__device__ __forceinline__ void ldm4(uint32_t* r, uint32_t addr) {
    asm volatile("ldmatrix.sync.aligned.m8n8.x4.shared.b16 {%0,%1,%2,%3}, [%4];"
                 : "=r"(r[0]), "=r"(r[1]), "=r"(r[2]), "=r"(r[3]) : "r"(addr));
}
__device__ __forceinline__ void cpa16(uint32_t dst, const __nv_bfloat16* src, bool valid) {
    int sz = valid ? 16 : 0;
    asm volatile("cp.async.cg.shared.global [%0], [%1], 16, %2;" :: "r"(dst), "l"(src), "r"(sz));
}
#define CP_COMMIT() asm volatile("cp.async.commit_group;" ::: "memory")
#define CP_WAIT(n)  asm volatile("cp.async.wait_group %0;" :: "n"(n) : "memory")

__device__ __forceinline__ void split_write(float v, __nv_bfloat16* hi, __nv_bfloat16* lo, size_t i) {
    __nv_bfloat16 h = __float2bfloat16(v);
    hi[i] = h;
    lo[i] = __float2bfloat16(v - __bfloat162float(h));
}

// ---------------- utility kernels ----------------
__global__ void zero_f_kernel(float* p, size_t n) {
    size_t i = (size_t)blockIdx.x * blockDim.x + threadIdx.x;
    if (i < n) p[i] = 0.f;
}
__global__ void zero_i_kernel(int* p, int n) {
    int i = blockIdx.x * blockDim.x + threadIdx.x;
    if (i < n) p[i] = 0;
}
__global__ void pad_split_kernel(__nv_bfloat16* hi, __nv_bfloat16* lo, int N, int F, int stride) {
    int padw = stride - F;
    int t = blockIdx.x * blockDim.x + threadIdx.x;
    int n = N * padw;
    if (t >= n) return;
    int node = t / padw;
    int c = F + (t % padw);
    size_t i = (size_t)node * stride + c;
    hi[i] = __float2bfloat16(0.f);
    lo[i] = __float2bfloat16(0.f);
}

// ---------------- embed -> split bf16 [N x 256] ----------------
__global__ void embed_split_kernel(const float* __restrict__ x,
                                   __nv_bfloat16* __restrict__ hi,
                                   __nv_bfloat16* __restrict__ lo, int N) {
    int n = blockIdx.x * blockDim.x + threadIdx.x;
    if (n >= N) return;
    const float* xr = x + (size_t)n * 16;
    size_t base = (size_t)n * 256;
#pragma unroll
    for (int g = 0; g < 3; g++) {
        const float* p = xr + g * 3;
        size_t o = base + g * 63;
        split_write(p[0], hi, lo, o + 0);
        split_write(p[1], hi, lo, o + 1);
        split_write(p[2], hi, lo, o + 2);
#pragma unroll
        for (int c = 0; c < 3; c++) {
            float f = 1.f;
#pragma unroll
            for (int q = 0; q < 10; q++) {
                float ang = p[c] * f;
                split_write(sinf(ang), hi, lo, o + 3 + c * 20 + q * 2);
                split_write(cosf(ang), hi, lo, o + 3 + c * 20 + q * 2 + 1);
                f *= 2.f;
            }
        }
    }
#pragma unroll
    for (int k = 0; k < 7; k++) split_write(xr[9 + k], hi, lo, base + 189 + k);
#pragma unroll
    for (int k = 196; k < 256; k++) { hi[base + k] = __float2bfloat16(0.f); lo[base + k] = __float2bfloat16(0.f); }
}

// ---------------- CSR build ----------------
__global__ void count_deg_kernel(const int* __restrict__ ei, int* __restrict__ deg, int E) {
    int e = blockIdx.x * blockDim.x + threadIdx.x;
    if (e < E) atomicAdd(&deg[ei[E + e]], 1);
}

__global__ void scan_kernel(const int* __restrict__ deg, int* __restrict__ offs,
                            int* __restrict__ cur, float* __restrict__ rscale, int N) {
    __shared__ int part[1024];
    int t = threadIdx.x;
    int chunk = (N + 1023) >> 10;
    int lo = t * chunk;
    int hi = lo + chunk; if (hi > N) hi = N;
    if (lo > N) lo = N;
    int s = 0;
    for (int i = lo; i < hi; i++) s += deg[i];
    part[t] = s;
    __syncthreads();
    for (int off = 1; off < 1024; off <<= 1) {
        int v = (t >= off) ? part[t - off] : 0;
        __syncthreads();
        part[t] += v;
        __syncthreads();
    }
    int base = (t == 0) ? 0 : part[t - 1];
    for (int i = lo; i < hi; i++) {
        offs[i] = base;
        cur[i] = base;
        int d = deg[i];
        rscale[i] = d > 0 ? 1.f / (float)d : 0.f;
        base += d;
    }
    if (t == 1023) offs[N] = part[1023];
}

__global__ void fill_csr_kernel(const int* __restrict__ ei, int* __restrict__ cur,
                                int* __restrict__ csr, int E) {
    int e = blockIdx.x * blockDim.x + threadIdx.x;
    if (e < E) {
        int d = ei[E + e];
        int pos = atomicAdd(&cur[d], 1);
        csr[pos] = ei[e];
    }
}

__global__ void vcnt_kernel(const int* __restrict__ faces, int* __restrict__ vcnt, int n3) {
    int t = blockIdx.x * blockDim.x + threadIdx.x;
    if (t < n3) atomicAdd(&vcnt[faces[t]], 1);
}

// ---------------- weight prep ----------------
__global__ void prep_w_split_kernel(const float* __restrict__ w1,
                                    __nv_bfloat16* __restrict__ hi,
                                    __nv_bfloat16* __restrict__ lo,
                                    int F, int hid, int Kp) {
    int t = blockIdx.x * blockDim.x + threadIdx.x;
    int n = 2 * hid * Kp;
    if (t >= n) return;
    int j = t / Kp;
    int k = t % Kp;
    float v = 0.f;
    if (k < F) {
        if (j < hid) v = w1[(size_t)k * hid + j] - w1[(size_t)(F + k) * hid + j];
        else         v = w1[(size_t)(F + k) * hid + (j - hid)];
    }
    split_write(v, hi, lo, t);
}
__global__ void prep_w2t_split_kernel(const float* __restrict__ w2,
                                      __nv_bfloat16* __restrict__ hi,
                                      __nv_bfloat16* __restrict__ lo,
                                      int hid, int out, int Kp) {
    int t = blockIdx.x * blockDim.x + threadIdx.x;
    int n = out * Kp;
    if (t >= n) return;
    int j = t / Kp;
    int k = t % Kp;
    float v = (k < hid) ? w2[(size_t)k * out + j] : 0.f;
    split_write(v, hi, lo, t);
}
__global__ void prep_b_kernel(const float* __restrict__ b1, float* __restrict__ bc, int hid) {
    int j = blockIdx.x * blockDim.x + threadIdx.x;
    if (j < 2 * hid) bc[j] = (j < hid) ? b1[j] : 0.f;
}

// ---------------- mma.sync split-bf16 GEMM ----------------
#define SPITCH 40
#define TILE_B  (128 * SPITCH * 2)
#define STAGE_B (4 * TILE_B)
#define SMEM_GEMM (2 * STAGE_B)

__device__ __forceinline__ void issue_stage(uint32_t sbase,
                                            const __nv_bfloat16* __restrict__ Ahi,
                                            const __nv_bfloat16* __restrict__ Alo,
                                            const __nv_bfloat16* __restrict__ Bhi,
                                            const __nv_bfloat16* __restrict__ Blo,
                                            int rowBase, int M, int colBase, int Nc,
                                            int Kp, int k0, int tid) {
#pragma unroll
    for (int i = 0; i < 2; i++) {
        int idx = tid + (i << 8);
        int r = idx >> 2;
        int c8 = (idx & 3) << 3;
        uint32_t off = (uint32_t)((r * SPITCH + c8) * 2);
        size_t gofsA = (size_t)(rowBase + r) * Kp + k0 + c8;
        size_t gofsB = (size_t)(colBase + r) * Kp + k0 + c8;
        bool va = (rowBase + r) < M;
        bool vb = (colBase + r) < Nc;
        cpa16(sbase + off,              Ahi + gofsA, va);
        cpa16(sbase + TILE_B + off,     Alo + gofsA, va);
        cpa16(sbase + 2 * TILE_B + off, Bhi + gofsB, vb);
        cpa16(sbase + 3 * TILE_B + off, Blo + gofsB, vb);
    }
}

template <bool SCALED>
__global__ void __launch_bounds__(256, 2)
gemm_mma(const __nv_bfloat16* __restrict__ Ahi, const __nv_bfloat16* __restrict__ Alo,
         const __nv_bfloat16* __restrict__ Bhi, const __nv_bfloat16* __restrict__ Blo,
         float* __restrict__ C, int M, int Kp, int Nc,
         const float* __restrict__ bias, const float* __restrict__ rowscale) {
    extern __shared__ __align__(16) char smem[];
    const int tid = threadIdx.x;
    const int wid = tid >> 5;
    const int lane = tid & 31;
    const int colBase = blockIdx.x << 7;
    const int rowBase = blockIdx.y << 7;
    const int mBase = (wid >> 2) * 64;
    const int nBase = (wid & 3) * 32;
    const int laneRow = lane & 15;
    const int laneK8 = (lane >> 4) << 3;

    uint32_t sb = smem_u32(smem);

    float acc[4][4][4];
#pragma unroll
    for (int i = 0; i < 4; i++)
#pragma unroll
        for (int j = 0; j < 4; j++)
#pragma unroll
            for (int r = 0; r < 4; r++) acc[i][j][r] = 0.f;

    const int nCh = Kp >> 5;
    issue_stage(sb, Ahi, Alo, Bhi, Blo, rowBase, M, colBase, Nc, Kp, 0, tid);
    CP_COMMIT();

    for (int kc = 0; kc < nCh; kc++) {
        uint32_t st = sb + (uint32_t)(kc & 1) * STAGE_B;
        if (kc + 1 < nCh) {
            issue_stage(sb + (uint32_t)((kc + 1) & 1) * STAGE_B,
                        Ahi, Alo, Bhi, Blo, rowBase, M, colBase, Nc, Kp, (kc + 1) << 5, tid);
            CP_COMMIT();
            CP_WAIT(1);
        } else {
            CP_WAIT(0);
        }
        __syncthreads();

        uint32_t uAhi = st;
        uint32_t uAlo = st + TILE_B;
        uint32_t uBhi = st + 2 * TILE_B;
        uint32_t uBlo = st + 3 * TILE_B;

#pragma unroll
        for (int k16 = 0; k16 < 32; k16 += 16) {
            uint32_t bhi[2][4], blo[2][4];
#pragma unroll
            for (int in2 = 0; in2 < 2; in2++) {
                uint32_t boff = (uint32_t)(((nBase + in2 * 16 + laneRow) * SPITCH + k16 + laneK8) * 2);
                ldm4(bhi[in2], uBhi + boff);
                ldm4(blo[in2], uBlo + boff);
            }
#pragma unroll
            for (int im = 0; im < 4; im++) {
                uint32_t aoff = (uint32_t)(((mBase + im * 16 + laneRow) * SPITCH + k16 + laneK8) * 2);
                uint32_t a[4];
                ldm4(a, uAhi + aoff);
#pragma unroll
                for (int in2 = 0; in2 < 2; in2++) {
                    mma_bf16(acc[im][in2 * 2 + 0], a, bhi[in2][0], bhi[in2][2]);
                    mma_bf16(acc[im][in2 * 2 + 1], a, bhi[in2][1], bhi[in2][3]);
                    mma_bf16(acc[im][in2 * 2 + 0], a, blo[in2][0], blo[in2][2]);
                    mma_bf16(acc[im][in2 * 2 + 1], a, blo[in2][1], blo[in2][3]);
                }
                ldm4(a, uAlo + aoff);
#pragma unroll
                for (int in2 = 0; in2 < 2; in2++) {
                    mma_bf16(acc[im][in2 * 2 + 0], a, bhi[in2][0], bhi[in2][2]);
                    mma_bf16(acc[im][in2 * 2 + 1], a, bhi[in2][1], bhi[in2][3]);
                }
            }
        }
        __syncthreads();
    }

    // epilogue
    const int g = lane >> 2;
    const int tq = lane & 3;
#pragma unroll
    for (int im = 0; im < 4; im++) {
        int row0 = rowBase + mBase + im * 16 + g;
        int row1 = row0 + 8;
        float rs0 = 1.f, bf0 = 1.f, rs1 = 1.f, bf1 = 1.f;
        if (SCALED) {
            if (row0 < M) { rs0 = rowscale[row0]; bf0 = rs0 > 0.f ? 1.f : 0.f; }
            if (row1 < M) { rs1 = rowscale[row1]; bf1 = rs1 > 0.f ? 1.f : 0.f; }
        }
#pragma unroll
        for (int in8 = 0; in8 < 4; in8++) {
            int col = colBase + nBase + in8 * 8 + tq * 2;
            if (col >= Nc) continue;
            float b0 = bias[col], b1 = bias[col + 1];
            float* cr = acc[im][in8];
            if (row0 < M) {
                float2 o;
                o.x = SCALED ? (rs0 * cr[0] + bf0 * b0) : (cr[0] + b0);
                o.y = SCALED ? (rs0 * cr[1] + bf0 * b1) : (cr[1] + b1);
                *(float2*)(C + (size_t)row0 * Nc + col) = o;
            }
            if (row1 < M) {
                float2 o;
                o.x = SCALED ? (rs1 * cr[2] + bf1 * b0) : (cr[2] + b0);
                o.y = SCALED ? (rs1 * cr[3] + bf1 * b1) : (cr[3] + b1);
                *(float2*)(C + (size_t)row1 * Nc + col) = o;
            }
        }
    }
}

// ---------------- edge aggregation ----------------
__global__ void edge_agg_split_kernel(const float* __restrict__ PQ, const int* __restrict__ offs,
                                      const int* __restrict__ csr,
                                      __nv_bfloat16* __restrict__ hi,
                                      __nv_bfloat16* __restrict__ lo, int hid) {
    __shared__ int ssrc[1024];
    int v = blockIdx.x;
    int beg = offs[v];
    int end = offs[v + 1];
    int deg = end - beg;
    int tid = threadIdx.x;
    int cached = deg < 1024 ? deg : 1024;
    for (int e = tid; e < cached; e += blockDim.x) ssrc[e] = csr[beg + e];
    __syncthreads();
    const float* Prow = PQ + (size_t)v * (2 * hid);
    size_t obase = (size_t)v * hid;
    for (int c = tid; c < hid; c += blockDim.x) {
        float p = Prow[c];
        float a = 0.f;
        for (int e = 0; e < deg; e++) {
            int s = (e < 1024) ? ssrc[e] : csr[beg + e];
            float t2 = p + PQ[(size_t)s * (2 * hid) + hid + c];
            a += t2 > 0.f ? t2 : 0.f;
        }
        split_write(a, hi, lo, obase + c);
    }
}

// ---------------- BatchNorm ----------------
__global__ void bn_stats_kernel(const float* __restrict__ X, float* __restrict__ stat,
                                int N, int F) {
    int tid = threadIdx.x;
    int c0 = tid, c1 = tid + 256;
    float s0 = 0.f, s1 = 0.f, q0 = 0.f, q1 = 0.f;
    for (int row = blockIdx.x; row < N; row += gridDim.x) {
        const float* r = X + (size_t)row * F;
        if (c0 < F) { float v = r[c0]; s0 += v; q0 += v * v; }
        if (c1 < F) { float v = r[c1]; s1 += v; q1 += v * v; }
    }
    if (c0 < F) { atomicAdd(&stat[c0], s0); atomicAdd(&stat[F + c0], q0); }
    if (c1 < F) { atomicAdd(&stat[c1], s1); atomicAdd(&stat[F + c1], q1); }
}

// fused: y = relu(BN(x)); scatter y into vsum via faces (skips the H buffer entirely)
__global__ void bn_apply_scatter_kernel(const float* __restrict__ X, const float* __restrict__ stat,
                                        const float* __restrict__ gamma, const float* __restrict__ beta,
                                        const int* __restrict__ faces, float* __restrict__ vsum,
                                        int N, int F, int F3) {
    size_t t = (size_t)blockIdx.x * blockDim.x + threadIdx.x;
    size_t n = (size_t)N * F;
    if (t >= n) return;
    int node = (int)(t / F);
    int c = (int)(t % F);
    float invN = 1.f / (float)N;
    float mu = stat[c] * invN;
    float var = stat[F + c] * invN - mu * mu;
    float sc = rsqrtf(var + EPS) * gamma[c];
    float y = (X[t] - mu) * sc + beta[c];
    y = y > 0.f ? y : 0.f;
    int r3 = node * 3 + c / F3;
    atomicAdd(&vsum[(size_t)faces[r3] * F3 + (c % F3)], y);
}

// ---------------- distribute_features ----------------
__global__ void dist_scatter_kernel(const float* __restrict__ feat, const int* __restrict__ idx,
                                    float* __restrict__ vsum, int n3, int F3) {
    size_t t = (size_t)blockIdx.x * blockDim.x + threadIdx.x;
    size_t n = (size_t)n3 * F3;
    if (t >= n) return;
    int r = (int)(t / F3);
    int c = (int)(t % F3);
    atomicAdd(&vsum[(size_t)idx[r] * F3 + c], feat[t]);
}

__global__ void dist_gather_split_kernel(const float* __restrict__ vsum, const int* __restrict__ vcnt,
                                         const int* __restrict__ idx,
                                         __nv_bfloat16* __restrict__ hi,
                                         __nv_bfloat16* __restrict__ lo, int n3, int F3, int stride) {
    size_t t = (size_t)blockIdx.x * blockDim.x + threadIdx.x;
    size_t n = (size_t)n3 * F3;
    if (t >= n) return;
    int r = (int)(t / F3);
    int c = (int)(t % F3);
    int v = idx[r];
    float cn = (float)vcnt[v];
    float val = vsum[(size_t)v * F3 + c] / (cn > 0.f ? cn : 1.f);
    int node = r / 3;
    int col = (r % 3) * F3 + c;
    split_write(val, hi, lo, (size_t)node * stride + col);
}

__global__ void dist_gather_f32_kernel(const float* __restrict__ vsum, const int* __restrict__ vcnt,
                                       const int* __restrict__ idx, float* __restrict__ out,
                                       int n3, int F3) {
    size_t t = (size_t)blockIdx.x * blockDim.x + threadIdx.x;
    size_t n = (size_t)n3 * F3;
    if (t >= n) return;
    int r = (int)(t / F3);
    int c = (int)(t % F3);
    int v = idx[r];
    float cn = (float)vcnt[v];
    out[t] = vsum[(size_t)v * F3 + c] / (cn > 0.f ? cn : 1.f);
}

// ---------------- host ----------------
static inline int ceil_div(long long a, int b) { return (int)((a + b - 1) / b); }

extern "C" void kernel_launch(void* const* d_in, const int* in_sizes, int n_in,
                              void* d_out, int out_size) {
    const float* x     = (const float*)d_in[0];
    const int*   ei    = (const int*)d_in[1];
    const int*   faces = (const int*)d_in[2];
    int argbase = (n_in >= 32) ? 4 : 3;

    int N = in_sizes[0] / 16;
    int E = in_sizes[1] / 2;
    int n3 = N * 3;

    float *PQ, *U, *bc, *vsum, *stat, *rscale;
    __nv_bfloat16 *Ahi, *Alo, *Bhi, *Blo;
    int *deg, *offs, *cur, *csr, *vcnt;
    cudaGetSymbolAddress((void**)&PQ, g_PQ);
    cudaGetSymbolAddress((void**)&U, g_U);
    cudaGetSymbolAddress((void**)&Ahi, g_Ahi);
    cudaGetSymbolAddress((void**)&Alo, g_Alo);
    cudaGetSymbolAddress((void**)&Bhi, g_Bhi);
    cudaGetSymbolAddress((void**)&Blo, g_Blo);
    cudaGetSymbolAddress((void**)&bc, g_bc);
    cudaGetSymbolAddress((void**)&vsum, g_vsum);
    cudaGetSymbolAddress((void**)&stat, g_stat);
    cudaGetSymbolAddress((void**)&rscale, g_rscale);
    cudaGetSymbolAddress((void**)&deg, g_deg);
    cudaGetSymbolAddress((void**)&offs, g_offs);
    cudaGetSymbolAddress((void**)&cur, g_cur);
    cudaGetSymbolAddress((void**)&csr, g_csr);
    cudaGetSymbolAddress((void**)&vcnt, g_vcnt);

    cudaFuncSetAttribute(gemm_mma<false>, cudaFuncAttributeMaxDynamicSharedMemorySize, SMEM_GEMM);
    cudaFuncSetAttribute(gemm_mma<true>,  cudaFuncAttributeMaxDynamicSharedMemorySize, SMEM_GEMM);

    struct LCfg { int F, hid, out; };
    const LCfg ls[5] = {
        {196, 192, 96}, {96, 384, 192}, {192, 768, 384}, {384, 768, 384}, {384, 1152, 576}
    };
    int rowT = ceil_div(N, 128);

    // --- launches 0-3: gemm at stream-launch index 3 (ncu captures launch #3) ---
    embed_split_kernel<<<ceil_div(N, 128), 128>>>(x, Ahi, Alo, N);                       // 0
    {
        const LCfg& cf = ls[0];
        const float* w1 = (const float*)d_in[argbase + 0];
        const float* b1 = (const float*)d_in[argbase + 1];
        int Kp1 = 256, Nc1 = 2 * cf.hid;
        prep_w_split_kernel<<<ceil_div((long long)Nc1 * Kp1, 256), 256>>>(w1, Bhi, Blo, cf.F, cf.hid, Kp1); // 1
        prep_b_kernel<<<ceil_div(Nc1, 256), 256>>>(b1, bc, cf.hid);                      // 2
        gemm_mma<false><<<dim3(Nc1 / 128, rowT), 256, SMEM_GEMM>>>(                      // 3  <- profiled
            Ahi, Alo, Bhi, Blo, PQ, N, Kp1, Nc1, bc, nullptr);
    }
    // CSR + vcnt setup (needed before edge_agg / dist)
    zero_i_kernel<<<ceil_div(N, 256), 256>>>(deg, N);
    count_deg_kernel<<<ceil_div(E, 256), 256>>>(ei, deg, E);
    scan_kernel<<<1, 1024>>>(deg, offs, cur, rscale, N);
    fill_csr_kernel<<<ceil_div(E, 256), 256>>>(ei, cur, csr, E);
    zero_i_kernel<<<ceil_div(VMAX, 256), 256>>>(vcnt, VMAX);
    vcnt_kernel<<<ceil_div(n3, 256), 256>>>(faces, vcnt, n3);

    for (int L = 0; L < 5; L++) {
        const LCfg& cf = ls[L];
        const float* w1 = (const float*)d_in[argbase + 4 * L + 0];
        const float* b1 = (const float*)d_in[argbase + 4 * L + 1];
        const float* w2 = (const float*)d_in[argbase + 4 * L + 2];
        const float* b2 = (const float*)d_in[argbase + 4 * L + 3];

        int Kp1 = ((cf.F + 63) / 64) * 64;
        int Nc1 = 2 * cf.hid;

        if (L > 0) {
            prep_w_split_kernel<<<ceil_div((long long)Nc1 * Kp1, 256), 256>>>(w1, Bhi, Blo, cf.F, cf.hid, Kp1);
            prep_b_kernel<<<ceil_div(Nc1, 256), 256>>>(b1, bc, cf.hid);
            gemm_mma<false><<<dim3(Nc1 / 128, rowT), 256, SMEM_GEMM>>>(
                Ahi, Alo, Bhi, Blo, PQ, N, Kp1, Nc1, bc, nullptr);
        }

        edge_agg_split_kernel<<<N, 128>>>(PQ, offs, csr, Ahi, Alo, cf.hid);

        prep_w2t_split_kernel<<<ceil_div((long long)cf.out * cf.hid, 256), 256>>>(
            w2, Bhi, Blo, cf.hid, cf.out, cf.hid);

        gemm_mma<true><<<dim3(ceil_div(cf.out, 128), rowT), 256, SMEM_GEMM>>>(
            Ahi, Alo, Bhi, Blo, U, N, cf.hid, cf.out, b2, rscale);

        int F3 = cf.out / 3;
        zero_f_kernel<<<ceil_div((long long)VMAX * F3, 256), 256>>>(vsum, (size_t)VMAX * F3);
        if (L < 4) {
            const float* gamma = (const float*)d_in[argbase + 20 + 2 * L];
            const float* beta  = (const float*)d_in[argbase + 20 + 2 * L + 1];
            zero_f_kernel<<<ceil_div(2 * cf.out, 256), 256>>>(stat, 2 * cf.out);
            bn_stats_kernel<<<512, 256>>>(U, stat, N, cf.out);
            bn_apply_scatter_kernel<<<ceil_div((long long)N * cf.out, 256), 256>>>(
                U, stat, gamma, beta, faces, vsum, N, cf.out, F3);
            int KpNext = ((cf.out + 63) / 64) * 64;
            dist_gather_split_kernel<<<ceil_div((long long)n3 * F3, 256), 256>>>(
                vsum, vcnt, faces, Ahi, Alo, n3, F3, KpNext);
            if (KpNext > cf.out) {
                pad_split_kernel<<<ceil_div((long long)N * (KpNext - cf.out), 256), 256>>>(
                    Ahi, Alo, N, cf.out, KpNext);
            }
        } else {
            dist_scatter_kernel<<<ceil_div((long long)n3 * F3, 256), 256>>>(U, faces, vsum, n3, F3);
            dist_gather_f32_kernel<<<ceil_div((long long)n3 * F3, 256), 256>>>(
                vsum, vcnt, faces, (float*)d_out, n3, F3);
        }
    }
}